// round 1
// baseline (speedup 1.0000x reference)
#include <cuda_runtime.h>
#include <math.h>

// Problem constants
#define B_    8
#define C_    512
#define H_    96
#define W_    96
#define HW_   9216           // 96*96
#define NTOK  73728          // B_*W_*H_  (tokens for the [*,512] GEMMs)
#define IMGN  37748736       // B_*C_*H_*W_ = NTOK*512
#define NHEAD 8
#define DH    64

// Scratch buffers (device globals; no dynamic allocation allowed)
__device__ float g_vqk[IMGN];
__device__ float g_bA[IMGN];
__device__ float g_bB[IMGN];
__device__ float g_bC[IMGN];

// ---------------------------------------------------------------------------
// Transpose kernels: (c,w) transpose for fixed (b,h)
// bchw_to_nhc: dst[((b*96+w)*96+h)*512+c] = src[((b*512+c)*96+h)*96+w]
// nhc_to_bchw: inverse direction
// grid (W/32=3, C/32=16, B*H=768), block (32,8)
// ---------------------------------------------------------------------------
__global__ void k_bchw_to_nhc(const float* __restrict__ src, float* __restrict__ dst) {
    __shared__ float tile[32][33];
    int bh = blockIdx.z;
    int b = bh / H_, h = bh % H_;
    int c0 = blockIdx.y * 32;
    int w0 = blockIdx.x * 32;
    int tx = threadIdx.x, ty = threadIdx.y;
#pragma unroll
    for (int k = 0; k < 4; ++k) {
        int c = c0 + ty + k * 8;
        tile[ty + k * 8][tx] =
            src[(((size_t)b * C_ + c) * H_ + h) * W_ + w0 + tx];
    }
    __syncthreads();
#pragma unroll
    for (int k = 0; k < 4; ++k) {
        int w = w0 + ty + k * 8;
        dst[(((size_t)b * W_ + w) * H_ + h) * C_ + c0 + tx] = tile[tx][ty + k * 8];
    }
}

__global__ void k_nhc_to_bchw(const float* __restrict__ src, float* __restrict__ dst) {
    __shared__ float tile[32][33];
    int bh = blockIdx.z;
    int b = bh / H_, h = bh % H_;
    int c0 = blockIdx.y * 32;
    int w0 = blockIdx.x * 32;
    int tx = threadIdx.x, ty = threadIdx.y;
#pragma unroll
    for (int k = 0; k < 4; ++k) {
        int w = w0 + ty + k * 8;
        tile[ty + k * 8][tx] =
            src[(((size_t)b * W_ + w) * H_ + h) * C_ + c0 + tx];
    }
    __syncthreads();
#pragma unroll
    for (int k = 0; k < 4; ++k) {
        int c = c0 + ty + k * 8;
        dst[(((size_t)b * C_ + c) * H_ + h) * W_ + w0 + tx] = tile[tx][ty + k * 8];
    }
}

// ---------------------------------------------------------------------------
// SGEMM: C[m,n] = sum_k A[m,k] * W[n,k]   (A:[M,512], W:[512,512] row-major)
// MODE 0: plain store to C[m*512+n]
// MODE 1: += extra[m*512+n]   (k = x@Wk^T + x)
// MODE 2: += extra[n]         (bias)
// MODE 3: pointwise-conv epilogue: v = clip(acc,0,6) + cr_gather; scatter to BCHW
// 128x128 tile, BK=8, 256 threads, 8x8 micro-tiles.
// ---------------------------------------------------------------------------
template <int MODE>
__global__ __launch_bounds__(256) void k_sgemm(
    const float* __restrict__ A, const float* __restrict__ Wt,
    float* __restrict__ C, const float* extra)
{
    __shared__ float sA[8][128];
    __shared__ float sB[8][128];
    const int tid = threadIdx.x;
    const int m0 = blockIdx.y * 128;
    const int n0 = blockIdx.x * 128;
    const int lr = tid >> 1;           // 0..127
    const int lc = (tid & 1) * 4;      // 0 or 4
    const int tx = tid & 15, ty = tid >> 4;

    const float* Ald = A + (size_t)(m0 + lr) * 512 + lc;
    const float* Wld = Wt + (size_t)(n0 + lr) * 512 + lc;

    float acc[8][8];
#pragma unroll
    for (int i = 0; i < 8; ++i)
#pragma unroll
        for (int j = 0; j < 8; ++j) acc[i][j] = 0.f;

    for (int kt = 0; kt < 512; kt += 8) {
        float4 a4 = *(const float4*)(Ald + kt);
        float4 b4 = *(const float4*)(Wld + kt);
        __syncthreads();
        sA[lc + 0][lr] = a4.x; sA[lc + 1][lr] = a4.y;
        sA[lc + 2][lr] = a4.z; sA[lc + 3][lr] = a4.w;
        sB[lc + 0][lr] = b4.x; sB[lc + 1][lr] = b4.y;
        sB[lc + 2][lr] = b4.z; sB[lc + 3][lr] = b4.w;
        __syncthreads();
#pragma unroll
        for (int kk = 0; kk < 8; ++kk) {
            float ar[8], br[8];
            *(float4*)(ar)     = *(const float4*)&sA[kk][ty * 8];
            *(float4*)(ar + 4) = *(const float4*)&sA[kk][ty * 8 + 4];
            *(float4*)(br)     = *(const float4*)&sB[kk][tx * 8];
            *(float4*)(br + 4) = *(const float4*)&sB[kk][tx * 8 + 4];
#pragma unroll
            for (int i = 0; i < 8; ++i)
#pragma unroll
                for (int j = 0; j < 8; ++j)
                    acc[i][j] = fmaf(ar[i], br[j], acc[i][j]);
        }
    }

    if (MODE == 3) {
        // m = token index = b*9216 + h*96 + w ; n = output channel
#pragma unroll
        for (int i = 0; i < 8; ++i) {
            int m = m0 + ty * 8 + i;
            int bb = m / HW_;
            int srow = m - bb * HW_;        // h*96 + w
            int hh = srow / W_;
            int ww = srow - hh * W_;
            const float* crp = extra + (((size_t)(bb * W_ + ww) * H_ + hh) * 512) + n0 + tx * 8;
            float* outp = C + (size_t)bb * (C_ * (size_t)HW_) + srow + (size_t)(n0 + tx * 8) * HW_;
#pragma unroll
            for (int j = 0; j < 8; ++j) {
                float v = fminf(fmaxf(acc[i][j], 0.f), 6.f) + crp[j];
                outp[(size_t)j * HW_] = v;
            }
        }
    } else {
#pragma unroll
        for (int i = 0; i < 8; ++i) {
            int m = m0 + ty * 8 + i;
            float* cp = C + (size_t)m * 512 + n0 + tx * 8;
#pragma unroll
            for (int j = 0; j < 8; ++j) {
                float v = acc[i][j];
                if (MODE == 1) v += extra[(size_t)m * 512 + n0 + tx * 8 + j];
                if (MODE == 2) v += extra[n0 + tx * 8 + j];
                cp[j] = v;
            }
        }
    }
}

// ---------------------------------------------------------------------------
// Attention: per (batch n, head): Q,K,V = [96,64] fp32 slices of [*,96,512]
// scores = QK^T/8, softmax over keys, O = P V. 256 threads, dynamic smem.
// smem: sQ[96][65], sK[96][65] (reused for V), sS[96][97]
// ---------------------------------------------------------------------------
#define SQ_LD 65
#define SS_LD 97
#define ATTN_SMEM ((2 * 96 * SQ_LD + 96 * SS_LD) * 4)

__global__ __launch_bounds__(256) void k_attn(
    const float* __restrict__ Q, const float* __restrict__ Kt,
    const float* __restrict__ Vt, float* __restrict__ O)
{
    extern __shared__ float sm[];
    float* sQ = sm;
    float* sK = sm + 96 * SQ_LD;
    float* sS = sm + 2 * 96 * SQ_LD;

    const int tid = threadIdx.x;
    const int n = blockIdx.x >> 3;
    const int hd = blockIdx.x & 7;
    const size_t base = (size_t)n * 96 * 512 + hd * DH;

    // load Q, K
    for (int i = tid; i < 96 * 64; i += 256) {
        int r = i >> 6, d = i & 63;
        sQ[r * SQ_LD + d] = Q[base + (size_t)r * 512 + d];
        sK[r * SQ_LD + d] = Kt[base + (size_t)r * 512 + d];
    }
    __syncthreads();

    const int tx = tid & 15, ty = tid >> 4;
    const int i0 = ty * 6, j0 = tx * 6;

    // scores
    {
        float acc[6][6];
#pragma unroll
        for (int a = 0; a < 6; ++a)
#pragma unroll
            for (int b = 0; b < 6; ++b) acc[a][b] = 0.f;
        for (int d = 0; d < 64; ++d) {
            float qv[6], kv[6];
#pragma unroll
            for (int a = 0; a < 6; ++a) qv[a] = sQ[(i0 + a) * SQ_LD + d];
#pragma unroll
            for (int b = 0; b < 6; ++b) kv[b] = sK[(j0 + b) * SQ_LD + d];
#pragma unroll
            for (int a = 0; a < 6; ++a)
#pragma unroll
                for (int b = 0; b < 6; ++b)
                    acc[a][b] = fmaf(qv[a], kv[b], acc[a][b]);
        }
#pragma unroll
        for (int a = 0; a < 6; ++a)
#pragma unroll
            for (int b = 0; b < 6; ++b)
                sS[(i0 + a) * SS_LD + j0 + b] = acc[a][b] * 0.125f;
    }
    __syncthreads();

    // load V into sK slot (all K reads complete) + softmax on sS
    for (int i = tid; i < 96 * 64; i += 256) {
        int r = i >> 6, d = i & 63;
        sK[r * SQ_LD + d] = Vt[base + (size_t)r * 512 + d];
    }
    {
        int warp = tid >> 5, lane = tid & 31;
        for (int r = warp; r < 96; r += 8) {
            float v0 = sS[r * SS_LD + lane];
            float v1 = sS[r * SS_LD + lane + 32];
            float v2 = sS[r * SS_LD + lane + 64];
            float mx = fmaxf(fmaxf(v0, v1), v2);
#pragma unroll
            for (int o = 16; o > 0; o >>= 1)
                mx = fmaxf(mx, __shfl_xor_sync(0xffffffffu, mx, o));
            float e0 = __expf(v0 - mx), e1 = __expf(v1 - mx), e2 = __expf(v2 - mx);
            float s = e0 + e1 + e2;
#pragma unroll
            for (int o = 16; o > 0; o >>= 1)
                s += __shfl_xor_sync(0xffffffffu, s, o);
            float inv = 1.f / s;
            sS[r * SS_LD + lane]      = e0 * inv;
            sS[r * SS_LD + lane + 32] = e1 * inv;
            sS[r * SS_LD + lane + 64] = e2 * inv;
        }
    }
    __syncthreads();

    // PV: out[i,d], thread tile 6(i) x 4(d)
    {
        const int d0 = tx * 4;
        float o[6][4];
#pragma unroll
        for (int a = 0; a < 6; ++a)
#pragma unroll
            for (int d = 0; d < 4; ++d) o[a][d] = 0.f;
        for (int j = 0; j < 96; ++j) {
            float sv[6], vv[4];
#pragma unroll
            for (int a = 0; a < 6; ++a) sv[a] = sS[(i0 + a) * SS_LD + j];
#pragma unroll
            for (int d = 0; d < 4; ++d) vv[d] = sK[j * SQ_LD + d0 + d];
#pragma unroll
            for (int a = 0; a < 6; ++a)
#pragma unroll
                for (int d = 0; d < 4; ++d)
                    o[a][d] = fmaf(sv[a], vv[d], o[a][d]);
        }
#pragma unroll
        for (int a = 0; a < 6; ++a)
#pragma unroll
            for (int d = 0; d < 4; ++d)
                O[base + (size_t)(i0 + a) * 512 + d0 + d] = o[a][d];
    }
}

// ---------------------------------------------------------------------------
// Depthwise 3x3 conv (SAME, zero pad) + BN(eval), write token-major [tok,512]
// ---------------------------------------------------------------------------
__global__ void k_dwconv(const float* __restrict__ x, const float* __restrict__ wgt,
                         const float* __restrict__ bg, const float* __restrict__ bb_,
                         const float* __restrict__ bm, const float* __restrict__ bv,
                         float* __restrict__ y)
{
    int idx = blockIdx.x * 256 + threadIdx.x;
    if (idx >= IMGN) return;
    int w = idx % W_;
    int h = (idx / W_) % H_;
    int c = (idx / HW_) % C_;
    int b = idx / (HW_ * C_);
    const float* xc = x + ((size_t)b * C_ + c) * HW_;
    const float* wc = wgt + c * 9;
    float acc = 0.f;
#pragma unroll
    for (int kh = 0; kh < 3; ++kh) {
        int hh = h + kh - 1;
        if (hh < 0 || hh >= H_) continue;
#pragma unroll
        for (int kw = 0; kw < 3; ++kw) {
            int ww = w + kw - 1;
            if (ww < 0 || ww >= W_) continue;
            acc = fmaf(xc[hh * W_ + ww], wc[kh * 3 + kw], acc);
        }
    }
    float sc = bg[c] * rsqrtf(bv[c] + 1e-5f);
    float v = (acc - bm[c]) * sc + bb_[c];
    y[((size_t)b * HW_ + h * W_ + w) * 512 + c] = v;
}

// ---------------------------------------------------------------------------
// Launch
// ---------------------------------------------------------------------------
extern "C" void kernel_launch(void* const* d_in, const int* in_sizes, int n_in,
                              void* d_out, int out_size)
{
    const float* x      = (const float*)d_in[0];
    const float* msa_Wk = (const float*)d_in[1];
    const float* msa_Wv = (const float*)d_in[2];
    const float* msa_Wo = (const float*)d_in[3];
    const float* cr_Wq  = (const float*)d_in[4];
    const float* cr_bq  = (const float*)d_in[5];
    const float* cr_Wv  = (const float*)d_in[6];
    const float* cr_Wo  = (const float*)d_in[7];
    const float* dw_w   = (const float*)d_in[8];
    const float* bn_g   = (const float*)d_in[9];
    const float* bn_b   = (const float*)d_in[10];
    const float* bn_m   = (const float*)d_in[11];
    const float* bn_v   = (const float*)d_in[12];
    const float* pw_w   = (const float*)d_in[13];
    float* out = (float*)d_out;

    float *vqk, *bA, *bB, *bC;
    cudaGetSymbolAddress((void**)&vqk, g_vqk);
    cudaGetSymbolAddress((void**)&bA, g_bA);
    cudaGetSymbolAddress((void**)&bB, g_bB);
    cudaGetSymbolAddress((void**)&bC, g_bC);

    cudaFuncSetAttribute(k_attn, cudaFuncAttributeMaxDynamicSharedMemorySize, ATTN_SMEM);

    dim3 tgrid(3, 16, B_ * H_), tblk(32, 8);
    dim3 ggrid(4, NTOK / 128), gblk(256);

    // 1. vqk = permute(x)
    k_bchw_to_nhc<<<tgrid, tblk>>>(x, vqk);
    // 2. K = vqk@Wk^T + vqk
    k_sgemm<1><<<ggrid, gblk>>>(vqk, msa_Wk, bA, vqk);
    // 3. V = vqk@Wv^T
    k_sgemm<0><<<ggrid, gblk>>>(vqk, msa_Wv, bB, nullptr);
    // 4. attn(vqk, K, V) -> bC
    k_attn<<<B_ * W_ * NHEAD, 256, ATTN_SMEM>>>(vqk, bA, bB, bC);
    // 5. O = attn@Wo^T -> bA
    k_sgemm<0><<<ggrid, gblk>>>(bC, msa_Wo, bA, nullptr);
    // 6. q_view buffer = nhc_to_bchw(O) -> bB (flat == q_view token-major)
    k_nhc_to_bchw<<<tgrid, tblk>>>(bA, bB);
    // 7. Q2 = q_view@Wq^T + bq -> bC
    k_sgemm<2><<<ggrid, gblk>>>(bB, cr_Wq, bC, cr_bq);
    // 8. KV = vqk@crWv^T -> bA
    k_sgemm<0><<<ggrid, gblk>>>(vqk, cr_Wv, bA, nullptr);
    // 9. attn(Q2, KV, KV) -> bB
    k_attn<<<B_ * W_ * NHEAD, 256, ATTN_SMEM>>>(bC, bA, bA, bB);
    // 10. CR = crattn@crWo^T -> bC  (nhc layout)
    k_sgemm<0><<<ggrid, gblk>>>(bB, cr_Wo, bC, nullptr);
    // 11. depthwise+BN -> bA (token-major)
    k_dwconv<<<(IMGN + 255) / 256, 256>>>(x, dw_w, bn_g, bn_b, bn_m, bn_v, bA);
    // 12. out = clip(bA@pw^T,0,6) + permute(CR), scattered to BCHW
    k_sgemm<3><<<ggrid, gblk>>>(bA, pw_w, out, bC);
}

// round 3
// speedup vs baseline: 2.1505x; 2.1505x over previous
#include <cuda_runtime.h>
#include <cstdint>
#include <math.h>

// Problem constants
#define B_    8
#define C_    512
#define H_    96
#define W_    96
#define HW_   9216
#define NTOK  73728          // B_*W_*H_
#define IMGN  37748736       // NTOK*512
#define NHEAD 8
#define DH    64

// Scratch buffers
__device__ float g_vqk[IMGN];
__device__ float g_bA[IMGN];
__device__ float g_bB[IMGN];
__device__ float g_bC[IMGN];

// ===========================================================================
// PTX helpers (all non-'a' features: cp.async sm_80+, mma.sync tf32 sm_80+)
// ===========================================================================
__device__ __forceinline__ uint32_t smem_u32(const void* p) {
    uint32_t a;
    asm("{ .reg .u64 t; cvta.to.shared.u64 t, %1; cvt.u32.u64 %0, t; }"
        : "=r"(a) : "l"(p));
    return a;
}
#define CP_ASYNC16(dst, src) \
    asm volatile("cp.async.cg.shared.global [%0], [%1], 16;" :: "r"(dst), "l"(src))
#define CP_COMMIT() asm volatile("cp.async.commit_group;" ::: "memory")
#define CP_WAIT0()  asm volatile("cp.async.wait_group 0;" ::: "memory")

__device__ __forceinline__ uint32_t f2tf32(float v) {
    uint32_t r;
    asm("cvt.rna.tf32.f32 %0, %1;" : "=r"(r) : "f"(v));
    return r;
}
__device__ __forceinline__ void mma_tf32(float* d, const uint32_t* a, const uint32_t* b) {
    asm volatile(
        "mma.sync.aligned.m16n8k8.row.col.f32.tf32.tf32.f32 "
        "{%0,%1,%2,%3}, {%4,%5,%6,%7}, {%8,%9}, {%0,%1,%2,%3};"
        : "+f"(d[0]), "+f"(d[1]), "+f"(d[2]), "+f"(d[3])
        : "r"(a[0]), "r"(a[1]), "r"(a[2]), "r"(a[3]), "r"(b[0]), "r"(b[1]));
}

// ===========================================================================
// Transpose kernels
// ===========================================================================
__global__ void k_bchw_to_nhc(const float* __restrict__ src, float* __restrict__ dst) {
    __shared__ float tile[32][33];
    int bh = blockIdx.z;
    int b = bh / H_, h = bh % H_;
    int c0 = blockIdx.y * 32;
    int w0 = blockIdx.x * 32;
    int tx = threadIdx.x, ty = threadIdx.y;
#pragma unroll
    for (int k = 0; k < 4; ++k) {
        int c = c0 + ty + k * 8;
        tile[ty + k * 8][tx] = src[(((size_t)b * C_ + c) * H_ + h) * W_ + w0 + tx];
    }
    __syncthreads();
#pragma unroll
    for (int k = 0; k < 4; ++k) {
        int w = w0 + ty + k * 8;
        dst[(((size_t)b * W_ + w) * H_ + h) * C_ + c0 + tx] = tile[tx][ty + k * 8];
    }
}

__global__ void k_nhc_to_bchw(const float* __restrict__ src, float* __restrict__ dst) {
    __shared__ float tile[32][33];
    int bh = blockIdx.z;
    int b = bh / H_, h = bh % H_;
    int c0 = blockIdx.y * 32;
    int w0 = blockIdx.x * 32;
    int tx = threadIdx.x, ty = threadIdx.y;
#pragma unroll
    for (int k = 0; k < 4; ++k) {
        int w = w0 + ty + k * 8;
        tile[ty + k * 8][tx] = src[(((size_t)b * W_ + w) * H_ + h) * C_ + c0 + tx];
    }
    __syncthreads();
#pragma unroll
    for (int k = 0; k < 4; ++k) {
        int c = c0 + ty + k * 8;
        dst[(((size_t)b * C_ + c) * H_ + h) * W_ + w0 + tx] = tile[tx][ty + k * 8];
    }
}

// ===========================================================================
// tf32 mma.sync GEMM: C[m,n] = sum_k A[m,k]*W[n,k]   A:[M,512]  W:[512,512]
// CTA 128x128, BK=32, 2-stage cp.async. 8 warps: 4(M) x 2(N), warp 32x64.
// MODE 0: plain  MODE 1: +=extra[m*512+n]  MODE 2: +=extra[n]
// MODE 3: clip(acc,0,6)+cr_gather -> scatter BCHW
// ===========================================================================
#define BK     32
#define SLD    36                       // smem row stride in floats (pad 4)
#define TILEF  (128 * SLD)              // floats per operand tile
#define GSMEM  (2 * 2 * TILEF * 4)      // 2 stages * (A+B) * bytes = 73728

__device__ __forceinline__ void load_tile_async(
    const float* __restrict__ A, const float* __restrict__ Wt,
    int m0, int n0, int kt, float* sA, float* sB, int tid)
{
#pragma unroll
    for (int it = 0; it < 4; ++it) {
        int c = it * 256 + tid;          // 0..1023
        int row = c >> 3;                // 0..127
        int seg = (c & 7) * 4;           // float offset in row
        uint32_t da = smem_u32(sA + row * SLD + seg);
        uint32_t db = smem_u32(sB + row * SLD + seg);
        CP_ASYNC16(da, A  + (size_t)(m0 + row) * 512 + kt + seg);
        CP_ASYNC16(db, Wt + (size_t)(n0 + row) * 512 + kt + seg);
    }
}

template <int MODE>
__global__ __launch_bounds__(256, 2) void k_mgemm(
    const float* __restrict__ A, const float* __restrict__ Wt,
    float* __restrict__ C, const float* __restrict__ extra)
{
    extern __shared__ float sm[];
    float* sA[2] = { sm,             sm + 2 * TILEF };
    float* sB[2] = { sm + TILEF,     sm + 3 * TILEF };

    const int tid = threadIdx.x;
    const int m0 = blockIdx.y * 128;
    const int n0 = blockIdx.x * 128;
    const int wid = tid >> 5, lane = tid & 31;
    const int mw = (wid & 3) * 32;       // warp M offset in tile
    const int nw = (wid >> 2) * 64;      // warp N offset in tile
    const int g = lane >> 2, tig = lane & 3;

    float d[2][8][4];
#pragma unroll
    for (int i = 0; i < 2; ++i)
#pragma unroll
        for (int j = 0; j < 8; ++j)
#pragma unroll
            for (int q = 0; q < 4; ++q) d[i][j][q] = 0.f;

    load_tile_async(A, Wt, m0, n0, 0, sA[0], sB[0], tid);
    CP_COMMIT();

#pragma unroll 1
    for (int t = 0; t < 16; ++t) {
        CP_WAIT0();
        __syncthreads();
        if (t + 1 < 16) {
            load_tile_async(A, Wt, m0, n0, (t + 1) * BK, sA[(t + 1) & 1], sB[(t + 1) & 1], tid);
            CP_COMMIT();
        }
        const float* cA = sA[t & 1];
        const float* cB = sB[t & 1];
#pragma unroll
        for (int kk = 0; kk < 4; ++kk) {
            const int k = kk * 8;
            uint32_t af[2][4], bf[8][2];
#pragma unroll
            for (int i = 0; i < 2; ++i) {
                const float* p = cA + (mw + i * 16 + g) * SLD + k + tig;
                af[i][0] = f2tf32(p[0]);
                af[i][2] = f2tf32(p[4]);
                af[i][1] = f2tf32(p[8 * SLD]);
                af[i][3] = f2tf32(p[8 * SLD + 4]);
            }
#pragma unroll
            for (int j = 0; j < 8; ++j) {
                const float* p = cB + (nw + j * 8 + g) * SLD + k + tig;
                bf[j][0] = f2tf32(p[0]);
                bf[j][1] = f2tf32(p[4]);
            }
#pragma unroll
            for (int i = 0; i < 2; ++i)
#pragma unroll
                for (int j = 0; j < 8; ++j)
                    mma_tf32(d[i][j], af[i], bf[j]);
        }
        __syncthreads();
    }

    // Epilogue. c-frag mapping: c0:(row g, col 2tig) c1:(g,2tig+1) c2:(g+8,2tig) c3:(g+8,2tig+1)
    if (MODE == 3) {
#pragma unroll
        for (int i = 0; i < 2; ++i) {
#pragma unroll
            for (int half = 0; half < 2; ++half) {
                int m = m0 + mw + i * 16 + g + half * 8;
                int bb = m / HW_;
                int srow = m - bb * HW_;
                int hh = srow / W_;
                int ww = srow - hh * W_;
                const float* crp = extra + (((size_t)(bb * W_ + ww) * H_ + hh) * 512);
                float* outp = C + (size_t)bb * 512 * HW_ + srow;
#pragma unroll
                for (int j = 0; j < 8; ++j) {
                    int nn = n0 + nw + j * 8 + 2 * tig;
                    float v0 = fminf(fmaxf(d[i][j][half * 2 + 0], 0.f), 6.f) + crp[nn];
                    float v1 = fminf(fmaxf(d[i][j][half * 2 + 1], 0.f), 6.f) + crp[nn + 1];
                    outp[(size_t)nn * HW_] = v0;
                    outp[(size_t)(nn + 1) * HW_] = v1;
                }
            }
        }
    } else {
#pragma unroll
        for (int i = 0; i < 2; ++i) {
#pragma unroll
            for (int half = 0; half < 2; ++half) {
                int m = m0 + mw + i * 16 + g + half * 8;
                float* cp = C + (size_t)m * 512;
                const float* ep = (MODE == 1) ? (extra + (size_t)m * 512) : extra;
#pragma unroll
                for (int j = 0; j < 8; ++j) {
                    int nn = n0 + nw + j * 8 + 2 * tig;
                    float v0 = d[i][j][half * 2 + 0];
                    float v1 = d[i][j][half * 2 + 1];
                    if (MODE == 1 || MODE == 2) { v0 += ep[nn]; v1 += ep[nn + 1]; }
                    *(float2*)(cp + nn) = make_float2(v0, v1);
                }
            }
        }
    }
}

// ===========================================================================
// Attention (unchanged, proven): per (n,head), 96x64 tiles, smem softmax
// ===========================================================================
#define SQ_LD 65
#define SS_LD 97
#define ATTN_SMEM ((2 * 96 * SQ_LD + 96 * SS_LD) * 4)

__global__ __launch_bounds__(256) void k_attn(
    const float* __restrict__ Q, const float* __restrict__ Kt,
    const float* __restrict__ Vt, float* __restrict__ O)
{
    extern __shared__ float sm[];
    float* sQ = sm;
    float* sK = sm + 96 * SQ_LD;
    float* sS = sm + 2 * 96 * SQ_LD;

    const int tid = threadIdx.x;
    const int n = blockIdx.x >> 3;
    const int hd = blockIdx.x & 7;
    const size_t base = (size_t)n * 96 * 512 + hd * DH;

    for (int i = tid; i < 96 * 64; i += 256) {
        int r = i >> 6, d = i & 63;
        sQ[r * SQ_LD + d] = Q[base + (size_t)r * 512 + d];
        sK[r * SQ_LD + d] = Kt[base + (size_t)r * 512 + d];
    }
    __syncthreads();

    const int tx = tid & 15, ty = tid >> 4;
    const int i0 = ty * 6, j0 = tx * 6;

    {
        float acc[6][6];
#pragma unroll
        for (int a = 0; a < 6; ++a)
#pragma unroll
            for (int b = 0; b < 6; ++b) acc[a][b] = 0.f;
        for (int d = 0; d < 64; ++d) {
            float qv[6], kv[6];
#pragma unroll
            for (int a = 0; a < 6; ++a) qv[a] = sQ[(i0 + a) * SQ_LD + d];
#pragma unroll
            for (int b = 0; b < 6; ++b) kv[b] = sK[(j0 + b) * SQ_LD + d];
#pragma unroll
            for (int a = 0; a < 6; ++a)
#pragma unroll
                for (int b = 0; b < 6; ++b)
                    acc[a][b] = fmaf(qv[a], kv[b], acc[a][b]);
        }
#pragma unroll
        for (int a = 0; a < 6; ++a)
#pragma unroll
            for (int b = 0; b < 6; ++b)
                sS[(i0 + a) * SS_LD + j0 + b] = acc[a][b] * 0.125f;
    }
    __syncthreads();

    for (int i = tid; i < 96 * 64; i += 256) {
        int r = i >> 6, d = i & 63;
        sK[r * SQ_LD + d] = Vt[base + (size_t)r * 512 + d];
    }
    {
        int warp = tid >> 5, lane = tid & 31;
        for (int r = warp; r < 96; r += 8) {
            float v0 = sS[r * SS_LD + lane];
            float v1 = sS[r * SS_LD + lane + 32];
            float v2 = sS[r * SS_LD + lane + 64];
            float mx = fmaxf(fmaxf(v0, v1), v2);
#pragma unroll
            for (int o = 16; o > 0; o >>= 1)
                mx = fmaxf(mx, __shfl_xor_sync(0xffffffffu, mx, o));
            float e0 = __expf(v0 - mx), e1 = __expf(v1 - mx), e2 = __expf(v2 - mx);
            float s = e0 + e1 + e2;
#pragma unroll
            for (int o = 16; o > 0; o >>= 1)
                s += __shfl_xor_sync(0xffffffffu, s, o);
            float inv = 1.f / s;
            sS[r * SS_LD + lane]      = e0 * inv;
            sS[r * SS_LD + lane + 32] = e1 * inv;
            sS[r * SS_LD + lane + 64] = e2 * inv;
        }
    }
    __syncthreads();

    {
        const int d0 = tx * 4;
        float o[6][4];
#pragma unroll
        for (int a = 0; a < 6; ++a)
#pragma unroll
            for (int d = 0; d < 4; ++d) o[a][d] = 0.f;
        for (int j = 0; j < 96; ++j) {
            float sv[6], vv[4];
#pragma unroll
            for (int a = 0; a < 6; ++a) sv[a] = sS[(i0 + a) * SS_LD + j];
#pragma unroll
            for (int d = 0; d < 4; ++d) vv[d] = sK[j * SQ_LD + d0 + d];
#pragma unroll
            for (int a = 0; a < 6; ++a)
#pragma unroll
                for (int d = 0; d < 4; ++d)
                    o[a][d] = fmaf(sv[a], vv[d], o[a][d]);
        }
#pragma unroll
        for (int a = 0; a < 6; ++a)
#pragma unroll
            for (int d = 0; d < 4; ++d)
                O[base + (size_t)(i0 + a) * 512 + d0 + d] = o[a][d];
    }
}

// ===========================================================================
// Depthwise 3x3 + BN (eval) -> token-major [tok, 512]
// ===========================================================================
__global__ void k_dwconv(const float* __restrict__ x, const float* __restrict__ wgt,
                         const float* __restrict__ bg, const float* __restrict__ bb_,
                         const float* __restrict__ bm, const float* __restrict__ bv,
                         float* __restrict__ y)
{
    int idx = blockIdx.x * 256 + threadIdx.x;
    if (idx >= IMGN) return;
    int w = idx % W_;
    int h = (idx / W_) % H_;
    int c = (idx / HW_) % C_;
    int b = idx / (HW_ * C_);
    const float* xc = x + ((size_t)b * C_ + c) * HW_;
    const float* wc = wgt + c * 9;
    float acc = 0.f;
#pragma unroll
    for (int kh = 0; kh < 3; ++kh) {
        int hh = h + kh - 1;
        if (hh < 0 || hh >= H_) continue;
#pragma unroll
        for (int kw = 0; kw < 3; ++kw) {
            int ww = w + kw - 1;
            if (ww < 0 || ww >= W_) continue;
            acc = fmaf(xc[hh * W_ + ww], wc[kh * 3 + kw], acc);
        }
    }
    float sc = bg[c] * rsqrtf(bv[c] + 1e-5f);
    float v = (acc - bm[c]) * sc + bb_[c];
    y[((size_t)b * HW_ + h * W_ + w) * 512 + c] = v;
}

// ===========================================================================
// Launch
// ===========================================================================
extern "C" void kernel_launch(void* const* d_in, const int* in_sizes, int n_in,
                              void* d_out, int out_size)
{
    const float* x      = (const float*)d_in[0];
    const float* msa_Wk = (const float*)d_in[1];
    const float* msa_Wv = (const float*)d_in[2];
    const float* msa_Wo = (const float*)d_in[3];
    const float* cr_Wq  = (const float*)d_in[4];
    const float* cr_bq  = (const float*)d_in[5];
    const float* cr_Wv  = (const float*)d_in[6];
    const float* cr_Wo  = (const float*)d_in[7];
    const float* dw_w   = (const float*)d_in[8];
    const float* bn_g   = (const float*)d_in[9];
    const float* bn_b   = (const float*)d_in[10];
    const float* bn_m   = (const float*)d_in[11];
    const float* bn_v   = (const float*)d_in[12];
    const float* pw_w   = (const float*)d_in[13];
    float* out = (float*)d_out;

    float *vqk, *bA, *bB, *bC;
    cudaGetSymbolAddress((void**)&vqk, g_vqk);
    cudaGetSymbolAddress((void**)&bA, g_bA);
    cudaGetSymbolAddress((void**)&bB, g_bB);
    cudaGetSymbolAddress((void**)&bC, g_bC);

    cudaFuncSetAttribute(k_attn, cudaFuncAttributeMaxDynamicSharedMemorySize, ATTN_SMEM);
    cudaFuncSetAttribute(k_mgemm<0>, cudaFuncAttributeMaxDynamicSharedMemorySize, GSMEM);
    cudaFuncSetAttribute(k_mgemm<1>, cudaFuncAttributeMaxDynamicSharedMemorySize, GSMEM);
    cudaFuncSetAttribute(k_mgemm<2>, cudaFuncAttributeMaxDynamicSharedMemorySize, GSMEM);
    cudaFuncSetAttribute(k_mgemm<3>, cudaFuncAttributeMaxDynamicSharedMemorySize, GSMEM);

    dim3 tgrid(3, 16, B_ * H_), tblk(32, 8);
    dim3 ggrid(4, NTOK / 128), gblk(256);

    // 1. vqk = permute(x)
    k_bchw_to_nhc<<<tgrid, tblk>>>(x, vqk);
    // 2. K = vqk@Wk^T + vqk
    k_mgemm<1><<<ggrid, gblk, GSMEM>>>(vqk, msa_Wk, bA, vqk);
    // 3. V = vqk@Wv^T
    k_mgemm<0><<<ggrid, gblk, GSMEM>>>(vqk, msa_Wv, bB, nullptr);
    // 4. attn(vqk, K, V) -> bC
    k_attn<<<B_ * W_ * NHEAD, 256, ATTN_SMEM>>>(vqk, bA, bB, bC);
    // 5. O = attn@Wo^T -> bA
    k_mgemm<0><<<ggrid, gblk, GSMEM>>>(bC, msa_Wo, bA, nullptr);
    // 6. q_view = nhc_to_bchw(O) -> bB
    k_nhc_to_bchw<<<tgrid, tblk>>>(bA, bB);
    // 7. Q2 = q_view@Wq^T + bq -> bC
    k_mgemm<2><<<ggrid, gblk, GSMEM>>>(bB, cr_Wq, bC, cr_bq);
    // 8. KV = vqk@crWv^T -> bA
    k_mgemm<0><<<ggrid, gblk, GSMEM>>>(vqk, cr_Wv, bA, nullptr);
    // 9. attn(Q2, KV, KV) -> bB
    k_attn<<<B_ * W_ * NHEAD, 256, ATTN_SMEM>>>(bC, bA, bA, bB);
    // 10. CR = crattn@crWo^T -> bC
    k_mgemm<0><<<ggrid, gblk, GSMEM>>>(bB, cr_Wo, bC, nullptr);
    // 11. depthwise+BN -> bA (token-major)
    k_dwconv<<<(IMGN + 255) / 256, 256>>>(x, dw_w, bn_g, bn_b, bn_m, bn_v, bA);
    // 12. out = clip(bA@pw^T,0,6) + permute(CR) -> BCHW
    k_mgemm<3><<<ggrid, gblk, GSMEM>>>(bA, pw_w, out, bC);
}

// round 4
// speedup vs baseline: 2.3510x; 1.0932x over previous
#include <cuda_runtime.h>
#include <cstdint>
#include <math.h>

// Problem constants
#define B_    8
#define C_    512
#define H_    96
#define W_    96
#define HW_   9216
#define NTOK  73728          // B_*W_*H_
#define IMGN  37748736       // NTOK*512
#define NHEAD 8
#define DH    64

// Scratch buffers
__device__ float g_vqk[IMGN];
__device__ float g_bA[IMGN];
__device__ float g_bB[IMGN];
__device__ float g_bC[IMGN];

// ===========================================================================
// PTX helpers (all non-'a' features: cp.async sm_80+, mma.sync tf32 sm_80+)
// ===========================================================================
__device__ __forceinline__ uint32_t smem_u32(const void* p) {
    uint32_t a;
    asm("{ .reg .u64 t; cvta.to.shared.u64 t, %1; cvt.u32.u64 %0, t; }"
        : "=r"(a) : "l"(p));
    return a;
}
#define CP_ASYNC16(dst, src) \
    asm volatile("cp.async.cg.shared.global [%0], [%1], 16;" :: "r"(dst), "l"(src))
#define CP_COMMIT() asm volatile("cp.async.commit_group;" ::: "memory")
#define CP_WAIT0()  asm volatile("cp.async.wait_group 0;" ::: "memory")

__device__ __forceinline__ uint32_t f2tf32(float v) {
    uint32_t r;
    asm("cvt.rna.tf32.f32 %0, %1;" : "=r"(r) : "f"(v));
    return r;
}
__device__ __forceinline__ void mma_tf32(float* d, const uint32_t* a, const uint32_t* b) {
    asm volatile(
        "mma.sync.aligned.m16n8k8.row.col.f32.tf32.tf32.f32 "
        "{%0,%1,%2,%3}, {%4,%5,%6,%7}, {%8,%9}, {%0,%1,%2,%3};"
        : "+f"(d[0]), "+f"(d[1]), "+f"(d[2]), "+f"(d[3])
        : "r"(a[0]), "r"(a[1]), "r"(a[2]), "r"(a[3]), "r"(b[0]), "r"(b[1]));
}

// ===========================================================================
// Transpose kernels
// ===========================================================================
__global__ void k_bchw_to_nhc(const float* __restrict__ src, float* __restrict__ dst) {
    __shared__ float tile[32][33];
    int bh = blockIdx.z;
    int b = bh / H_, h = bh % H_;
    int c0 = blockIdx.y * 32;
    int w0 = blockIdx.x * 32;
    int tx = threadIdx.x, ty = threadIdx.y;
#pragma unroll
    for (int k = 0; k < 4; ++k) {
        int c = c0 + ty + k * 8;
        tile[ty + k * 8][tx] = src[(((size_t)b * C_ + c) * H_ + h) * W_ + w0 + tx];
    }
    __syncthreads();
#pragma unroll
    for (int k = 0; k < 4; ++k) {
        int w = w0 + ty + k * 8;
        dst[(((size_t)b * W_ + w) * H_ + h) * C_ + c0 + tx] = tile[tx][ty + k * 8];
    }
}

__global__ void k_nhc_to_bchw(const float* __restrict__ src, float* __restrict__ dst) {
    __shared__ float tile[32][33];
    int bh = blockIdx.z;
    int b = bh / H_, h = bh % H_;
    int c0 = blockIdx.y * 32;
    int w0 = blockIdx.x * 32;
    int tx = threadIdx.x, ty = threadIdx.y;
#pragma unroll
    for (int k = 0; k < 4; ++k) {
        int w = w0 + ty + k * 8;
        tile[ty + k * 8][tx] = src[(((size_t)b * W_ + w) * H_ + h) * C_ + c0 + tx];
    }
    __syncthreads();
#pragma unroll
    for (int k = 0; k < 4; ++k) {
        int c = c0 + ty + k * 8;
        dst[(((size_t)b * C_ + c) * H_ + h) * W_ + w0 + tx] = tile[tx][ty + k * 8];
    }
}

// ===========================================================================
// tf32 mma.sync GEMM (unchanged from R3 passing version)
// ===========================================================================
#define BK     32
#define SLD    36
#define TILEF  (128 * SLD)
#define GSMEM  (2 * 2 * TILEF * 4)

__device__ __forceinline__ void load_tile_async(
    const float* __restrict__ A, const float* __restrict__ Wt,
    int m0, int n0, int kt, float* sA, float* sB, int tid)
{
#pragma unroll
    for (int it = 0; it < 4; ++it) {
        int c = it * 256 + tid;
        int row = c >> 3;
        int seg = (c & 7) * 4;
        uint32_t da = smem_u32(sA + row * SLD + seg);
        uint32_t db = smem_u32(sB + row * SLD + seg);
        CP_ASYNC16(da, A  + (size_t)(m0 + row) * 512 + kt + seg);
        CP_ASYNC16(db, Wt + (size_t)(n0 + row) * 512 + kt + seg);
    }
}

template <int MODE>
__global__ __launch_bounds__(256, 2) void k_mgemm(
    const float* __restrict__ A, const float* __restrict__ Wt,
    float* __restrict__ C, const float* __restrict__ extra)
{
    extern __shared__ float sm[];
    float* sA[2] = { sm,             sm + 2 * TILEF };
    float* sB[2] = { sm + TILEF,     sm + 3 * TILEF };

    const int tid = threadIdx.x;
    const int m0 = blockIdx.y * 128;
    const int n0 = blockIdx.x * 128;
    const int wid = tid >> 5, lane = tid & 31;
    const int mw = (wid & 3) * 32;
    const int nw = (wid >> 2) * 64;
    const int g = lane >> 2, tig = lane & 3;

    float d[2][8][4];
#pragma unroll
    for (int i = 0; i < 2; ++i)
#pragma unroll
        for (int j = 0; j < 8; ++j)
#pragma unroll
            for (int q = 0; q < 4; ++q) d[i][j][q] = 0.f;

    load_tile_async(A, Wt, m0, n0, 0, sA[0], sB[0], tid);
    CP_COMMIT();

#pragma unroll 1
    for (int t = 0; t < 16; ++t) {
        CP_WAIT0();
        __syncthreads();
        if (t + 1 < 16) {
            load_tile_async(A, Wt, m0, n0, (t + 1) * BK, sA[(t + 1) & 1], sB[(t + 1) & 1], tid);
            CP_COMMIT();
        }
        const float* cA = sA[t & 1];
        const float* cB = sB[t & 1];
#pragma unroll
        for (int kk = 0; kk < 4; ++kk) {
            const int k = kk * 8;
            uint32_t af[2][4], bf[8][2];
#pragma unroll
            for (int i = 0; i < 2; ++i) {
                const float* p = cA + (mw + i * 16 + g) * SLD + k + tig;
                af[i][0] = f2tf32(p[0]);
                af[i][2] = f2tf32(p[4]);
                af[i][1] = f2tf32(p[8 * SLD]);
                af[i][3] = f2tf32(p[8 * SLD + 4]);
            }
#pragma unroll
            for (int j = 0; j < 8; ++j) {
                const float* p = cB + (nw + j * 8 + g) * SLD + k + tig;
                bf[j][0] = f2tf32(p[0]);
                bf[j][1] = f2tf32(p[4]);
            }
#pragma unroll
            for (int i = 0; i < 2; ++i)
#pragma unroll
                for (int j = 0; j < 8; ++j)
                    mma_tf32(d[i][j], af[i], bf[j]);
        }
        __syncthreads();
    }

    if (MODE == 3) {
#pragma unroll
        for (int i = 0; i < 2; ++i) {
#pragma unroll
            for (int half = 0; half < 2; ++half) {
                int m = m0 + mw + i * 16 + g + half * 8;
                int bb = m / HW_;
                int srow = m - bb * HW_;
                int hh = srow / W_;
                int ww = srow - hh * W_;
                const float* crp = extra + (((size_t)(bb * W_ + ww) * H_ + hh) * 512);
                float* outp = C + (size_t)bb * 512 * HW_ + srow;
#pragma unroll
                for (int j = 0; j < 8; ++j) {
                    int nn = n0 + nw + j * 8 + 2 * tig;
                    float v0 = fminf(fmaxf(d[i][j][half * 2 + 0], 0.f), 6.f) + crp[nn];
                    float v1 = fminf(fmaxf(d[i][j][half * 2 + 1], 0.f), 6.f) + crp[nn + 1];
                    outp[(size_t)nn * HW_] = v0;
                    outp[(size_t)(nn + 1) * HW_] = v1;
                }
            }
        }
    } else {
#pragma unroll
        for (int i = 0; i < 2; ++i) {
#pragma unroll
            for (int half = 0; half < 2; ++half) {
                int m = m0 + mw + i * 16 + g + half * 8;
                float* cp = C + (size_t)m * 512;
                const float* ep = (MODE == 1) ? (extra + (size_t)m * 512) : extra;
#pragma unroll
                for (int j = 0; j < 8; ++j) {
                    int nn = n0 + nw + j * 8 + 2 * tig;
                    float v0 = d[i][j][half * 2 + 0];
                    float v1 = d[i][j][half * 2 + 1];
                    if (MODE == 1 || MODE == 2) { v0 += ep[nn]; v1 += ep[nn + 1]; }
                    *(float2*)(cp + nn) = make_float2(v0, v1);
                }
            }
        }
    }
}

// ===========================================================================
// Tensor-core attention: per (n,head) block, 192 threads = 6 warps.
// Warp w owns 16-row strip. QK^T (tf32 mma) -> S aliased over dead Q/K smem
// -> warp-local softmax -> PV (tf32 mma, V transposed in smem).
// ===========================================================================
#define ALD 68          // Q/K smem row stride (floats)
#define VLD 100         // Vt / S smem row stride (floats)
#define ATTN_T_SMEM ((2 * 96 * ALD + 64 * VLD) * 4)   // 77824 B

__global__ __launch_bounds__(192, 2) void k_attn_t(
    const float* __restrict__ Q, const float* __restrict__ Kt,
    const float* __restrict__ Vt, float* __restrict__ O)
{
    extern __shared__ float sm[];
    float* sQ = sm;                       // 96 x 68
    float* sK = sm + 96 * ALD;            // 96 x 68
    float* sV = sm + 2 * 96 * ALD;        // 64 x 100 (V^T: [d][key])
    float* sS = sm;                       // 96 x 100 (aliases Q+K region)

    const int tid = threadIdx.x;
    const int n = blockIdx.x >> 3;
    const int hd = blockIdx.x & 7;
    const size_t base = (size_t)n * 96 * 512 + hd * DH;

    // Load Q (pre-scaled by 1/8), K as float4; V transposed (scalar).
    for (int i = tid; i < 96 * 16; i += 192) {
        int r = i >> 4, c = (i & 15) * 4;
        float4 q4 = *(const float4*)(Q + base + (size_t)r * 512 + c);
        q4.x *= 0.125f; q4.y *= 0.125f; q4.z *= 0.125f; q4.w *= 0.125f;
        *(float4*)(sQ + r * ALD + c) = q4;
        *(float4*)(sK + r * ALD + c) = *(const float4*)(Kt + base + (size_t)r * 512 + c);
    }
    for (int i = tid; i < 96 * 64; i += 192) {
        int key = i >> 6, d = i & 63;
        sV[d * VLD + key] = Vt[base + (size_t)key * 512 + d];
    }
    __syncthreads();

    const int wid = tid / 32, lane = tid % 32;
    const int g = lane >> 2, tig = lane & 3;
    const int m0 = wid * 16;

    // --- scores: S[m0..m0+15][0..95] = Q' K^T ---
    float dS[12][4];
#pragma unroll
    for (int j = 0; j < 12; ++j)
#pragma unroll
        for (int q = 0; q < 4; ++q) dS[j][q] = 0.f;

#pragma unroll
    for (int kk = 0; kk < 8; ++kk) {
        const int k = kk * 8;
        uint32_t a[4];
        const float* pa = sQ + (m0 + g) * ALD + k + tig;
        a[0] = f2tf32(pa[0]);
        a[1] = f2tf32(pa[8 * ALD]);
        a[2] = f2tf32(pa[4]);
        a[3] = f2tf32(pa[8 * ALD + 4]);
#pragma unroll
        for (int j = 0; j < 12; ++j) {
            const float* pb = sK + (j * 8 + g) * ALD + k + tig;
            uint32_t b[2];
            b[0] = f2tf32(pb[0]);
            b[1] = f2tf32(pb[4]);
            mma_tf32(dS[j], a, b);
        }
    }
    __syncthreads();   // all warps done reading Q/K; S may overwrite

#pragma unroll
    for (int j = 0; j < 12; ++j) {
        int col = j * 8 + 2 * tig;
        *(float2*)(sS + (m0 + g) * VLD + col)     = make_float2(dS[j][0], dS[j][1]);
        *(float2*)(sS + (m0 + g + 8) * VLD + col) = make_float2(dS[j][2], dS[j][3]);
    }
    __syncwarp();

    // --- softmax on own 16 rows ---
#pragma unroll 1
    for (int rr = 0; rr < 16; ++rr) {
        float* row = sS + (m0 + rr) * VLD;
        float v0 = row[lane], v1 = row[lane + 32], v2 = row[lane + 64];
        float mx = fmaxf(v0, fmaxf(v1, v2));
#pragma unroll
        for (int o = 16; o > 0; o >>= 1)
            mx = fmaxf(mx, __shfl_xor_sync(0xffffffffu, mx, o));
        float e0 = __expf(v0 - mx), e1 = __expf(v1 - mx), e2 = __expf(v2 - mx);
        float s = e0 + e1 + e2;
#pragma unroll
        for (int o = 16; o > 0; o >>= 1)
            s += __shfl_xor_sync(0xffffffffu, s, o);
        float inv = 1.f / s;
        row[lane] = e0 * inv; row[lane + 32] = e1 * inv; row[lane + 64] = e2 * inv;
    }
    __syncwarp();

    // --- PV: O[m0..m0+15][0..63] = P V  (A = P rows, B = sV: [d][key]) ---
    float dO[8][4];
#pragma unroll
    for (int j = 0; j < 8; ++j)
#pragma unroll
        for (int q = 0; q < 4; ++q) dO[j][q] = 0.f;

#pragma unroll
    for (int kk = 0; kk < 12; ++kk) {
        const int k = kk * 8;
        uint32_t a[4];
        const float* pa = sS + (m0 + g) * VLD + k + tig;
        a[0] = f2tf32(pa[0]);
        a[1] = f2tf32(pa[8 * VLD]);
        a[2] = f2tf32(pa[4]);
        a[3] = f2tf32(pa[8 * VLD + 4]);
#pragma unroll
        for (int j = 0; j < 8; ++j) {
            const float* pb = sV + (j * 8 + g) * VLD + k + tig;
            uint32_t b[2];
            b[0] = f2tf32(pb[0]);
            b[1] = f2tf32(pb[4]);
            mma_tf32(dO[j], a, b);
        }
    }

#pragma unroll
    for (int j = 0; j < 8; ++j) {
        int col = j * 8 + 2 * tig;
        *(float2*)(O + base + (size_t)(m0 + g) * 512 + col)     = make_float2(dO[j][0], dO[j][1]);
        *(float2*)(O + base + (size_t)(m0 + g + 8) * 512 + col) = make_float2(dO[j][2], dO[j][3]);
    }
}

// ===========================================================================
// Depthwise 3x3 + BN (eval) -> token-major [tok, 512]
// ===========================================================================
__global__ void k_dwconv(const float* __restrict__ x, const float* __restrict__ wgt,
                         const float* __restrict__ bg, const float* __restrict__ bb_,
                         const float* __restrict__ bm, const float* __restrict__ bv,
                         float* __restrict__ y)
{
    int idx = blockIdx.x * 256 + threadIdx.x;
    if (idx >= IMGN) return;
    int w = idx % W_;
    int h = (idx / W_) % H_;
    int c = (idx / HW_) % C_;
    int b = idx / (HW_ * C_);
    const float* xc = x + ((size_t)b * C_ + c) * HW_;
    const float* wc = wgt + c * 9;
    float acc = 0.f;
#pragma unroll
    for (int kh = 0; kh < 3; ++kh) {
        int hh = h + kh - 1;
        if (hh < 0 || hh >= H_) continue;
#pragma unroll
        for (int kw = 0; kw < 3; ++kw) {
            int ww = w + kw - 1;
            if (ww < 0 || ww >= W_) continue;
            acc = fmaf(xc[hh * W_ + ww], wc[kh * 3 + kw], acc);
        }
    }
    float sc = bg[c] * rsqrtf(bv[c] + 1e-5f);
    float v = (acc - bm[c]) * sc + bb_[c];
    y[((size_t)b * HW_ + h * W_ + w) * 512 + c] = v;
}

// ===========================================================================
// Launch
// ===========================================================================
extern "C" void kernel_launch(void* const* d_in, const int* in_sizes, int n_in,
                              void* d_out, int out_size)
{
    const float* x      = (const float*)d_in[0];
    const float* msa_Wk = (const float*)d_in[1];
    const float* msa_Wv = (const float*)d_in[2];
    const float* msa_Wo = (const float*)d_in[3];
    const float* cr_Wq  = (const float*)d_in[4];
    const float* cr_bq  = (const float*)d_in[5];
    const float* cr_Wv  = (const float*)d_in[6];
    const float* cr_Wo  = (const float*)d_in[7];
    const float* dw_w   = (const float*)d_in[8];
    const float* bn_g   = (const float*)d_in[9];
    const float* bn_b   = (const float*)d_in[10];
    const float* bn_m   = (const float*)d_in[11];
    const float* bn_v   = (const float*)d_in[12];
    const float* pw_w   = (const float*)d_in[13];
    float* out = (float*)d_out;

    float *vqk, *bA, *bB, *bC;
    cudaGetSymbolAddress((void**)&vqk, g_vqk);
    cudaGetSymbolAddress((void**)&bA, g_bA);
    cudaGetSymbolAddress((void**)&bB, g_bB);
    cudaGetSymbolAddress((void**)&bC, g_bC);

    cudaFuncSetAttribute(k_attn_t, cudaFuncAttributeMaxDynamicSharedMemorySize, ATTN_T_SMEM);
    cudaFuncSetAttribute(k_mgemm<0>, cudaFuncAttributeMaxDynamicSharedMemorySize, GSMEM);
    cudaFuncSetAttribute(k_mgemm<1>, cudaFuncAttributeMaxDynamicSharedMemorySize, GSMEM);
    cudaFuncSetAttribute(k_mgemm<2>, cudaFuncAttributeMaxDynamicSharedMemorySize, GSMEM);
    cudaFuncSetAttribute(k_mgemm<3>, cudaFuncAttributeMaxDynamicSharedMemorySize, GSMEM);

    dim3 tgrid(3, 16, B_ * H_), tblk(32, 8);
    dim3 ggrid(4, NTOK / 128), gblk(256);

    // 1. vqk = permute(x)
    k_bchw_to_nhc<<<tgrid, tblk>>>(x, vqk);
    // 2. K = vqk@Wk^T + vqk
    k_mgemm<1><<<ggrid, gblk, GSMEM>>>(vqk, msa_Wk, bA, vqk);
    // 3. V = vqk@Wv^T
    k_mgemm<0><<<ggrid, gblk, GSMEM>>>(vqk, msa_Wv, bB, nullptr);
    // 4. attn(vqk, K, V) -> bC
    k_attn_t<<<B_ * W_ * NHEAD, 192, ATTN_T_SMEM>>>(vqk, bA, bB, bC);
    // 5. O = attn@Wo^T -> bA
    k_mgemm<0><<<ggrid, gblk, GSMEM>>>(bC, msa_Wo, bA, nullptr);
    // 6. q_view = nhc_to_bchw(O) -> bB
    k_nhc_to_bchw<<<tgrid, tblk>>>(bA, bB);
    // 7. Q2 = q_view@Wq^T + bq -> bC
    k_mgemm<2><<<ggrid, gblk, GSMEM>>>(bB, cr_Wq, bC, cr_bq);
    // 8. KV = vqk@crWv^T -> bA
    k_mgemm<0><<<ggrid, gblk, GSMEM>>>(vqk, cr_Wv, bA, nullptr);
    // 9. attn(Q2, KV, KV) -> bB
    k_attn_t<<<B_ * W_ * NHEAD, 192, ATTN_T_SMEM>>>(bC, bA, bA, bB);
    // 10. CR = crattn@crWo^T -> bC
    k_mgemm<0><<<ggrid, gblk, GSMEM>>>(bB, cr_Wo, bC, nullptr);
    // 11. depthwise+BN -> bA (token-major)
    k_dwconv<<<(IMGN + 255) / 256, 256>>>(x, dw_w, bn_g, bn_b, bn_m, bn_v, bA);
    // 12. out = clip(bA@pw^T,0,6) + permute(CR) -> BCHW
    k_mgemm<3><<<ggrid, gblk, GSMEM>>>(bA, pw_w, out, bC);
}

// round 6
// speedup vs baseline: 2.5335x; 1.0776x over previous
#include <cuda_runtime.h>
#include <cstdint>
#include <math.h>

// Problem constants
#define B_    8
#define C_    512
#define H_    96
#define W_    96
#define HW_   9216
#define NTOK  73728          // B_*W_*H_
#define IMGN  37748736       // NTOK*512
#define NHEAD 8
#define DH    64

// Scratch buffers
__device__ float g_vqk[IMGN];
__device__ float g_bA[IMGN];
__device__ float g_bB[IMGN];
__device__ float g_bC[IMGN];

// ===========================================================================
// PTX helpers (all non-'a' features: cp.async sm_80+, mma.sync tf32 sm_80+)
// ===========================================================================
__device__ __forceinline__ uint32_t smem_u32(const void* p) {
    uint32_t a;
    asm("{ .reg .u64 t; cvta.to.shared.u64 t, %1; cvt.u32.u64 %0, t; }"
        : "=r"(a) : "l"(p));
    return a;
}
#define CP_ASYNC16(dst, src) \
    asm volatile("cp.async.cg.shared.global [%0], [%1], 16;" :: "r"(dst), "l"(src))
#define CP_COMMIT() asm volatile("cp.async.commit_group;" ::: "memory")
#define CP_WAIT0()  asm volatile("cp.async.wait_group 0;" ::: "memory")
#define CP_WAIT1()  asm volatile("cp.async.wait_group 1;" ::: "memory")

__device__ __forceinline__ uint32_t f2tf32(float v) {
    uint32_t r;
    asm("cvt.rna.tf32.f32 %0, %1;" : "=r"(r) : "f"(v));
    return r;
}
__device__ __forceinline__ void mma_tf32(float* d, const uint32_t* a, const uint32_t* b) {
    asm volatile(
        "mma.sync.aligned.m16n8k8.row.col.f32.tf32.tf32.f32 "
        "{%0,%1,%2,%3}, {%4,%5,%6,%7}, {%8,%9}, {%0,%1,%2,%3};"
        : "+f"(d[0]), "+f"(d[1]), "+f"(d[2]), "+f"(d[3])
        : "r"(a[0]), "r"(a[1]), "r"(a[2]), "r"(a[3]), "r"(b[0]), "r"(b[1]));
}

// ===========================================================================
// Transpose kernels
// ===========================================================================
__global__ void k_bchw_to_nhc(const float* __restrict__ src, float* __restrict__ dst) {
    __shared__ float tile[32][33];
    int bh = blockIdx.z;
    int b = bh / H_, h = bh % H_;
    int c0 = blockIdx.y * 32;
    int w0 = blockIdx.x * 32;
    int tx = threadIdx.x, ty = threadIdx.y;
#pragma unroll
    for (int k = 0; k < 4; ++k) {
        int c = c0 + ty + k * 8;
        tile[ty + k * 8][tx] = src[(((size_t)b * C_ + c) * H_ + h) * W_ + w0 + tx];
    }
    __syncthreads();
#pragma unroll
    for (int k = 0; k < 4; ++k) {
        int w = w0 + ty + k * 8;
        dst[(((size_t)b * W_ + w) * H_ + h) * C_ + c0 + tx] = tile[tx][ty + k * 8];
    }
}

__global__ void k_nhc_to_bchw(const float* __restrict__ src, float* __restrict__ dst) {
    __shared__ float tile[32][33];
    int bh = blockIdx.z;
    int b = bh / H_, h = bh % H_;
    int c0 = blockIdx.y * 32;
    int w0 = blockIdx.x * 32;
    int tx = threadIdx.x, ty = threadIdx.y;
#pragma unroll
    for (int k = 0; k < 4; ++k) {
        int w = w0 + ty + k * 8;
        tile[ty + k * 8][tx] = src[(((size_t)b * W_ + w) * H_ + h) * C_ + c0 + tx];
    }
    __syncthreads();
#pragma unroll
    for (int k = 0; k < 4; ++k) {
        int c = c0 + ty + k * 8;
        dst[(((size_t)b * C_ + c) * H_ + h) * W_ + w0 + tx] = tile[tx][ty + k * 8];
    }
}

// ===========================================================================
// tf32 mma.sync GEMM: 3-stage cp.async pipeline, one barrier per K-step.
// C[m,n] = sum_k A[m,k]*W[n,k]. CTA 128x128, BK=32, 8 warps 4(M)x2(N).
// ===========================================================================
#define BK     32
#define SLD    36
#define TILEF  (128 * SLD)
#define GSMEM  (3 * 2 * TILEF * 4)     // 110592 B -> 2 CTAs/SM

__device__ __forceinline__ void load_tile_async(
    const float* __restrict__ A, const float* __restrict__ Wt,
    int m0, int n0, int kt, float* sA, float* sB, int tid)
{
#pragma unroll
    for (int it = 0; it < 4; ++it) {
        int c = it * 256 + tid;
        int row = c >> 3;
        int seg = (c & 7) * 4;
        uint32_t da = smem_u32(sA + row * SLD + seg);
        uint32_t db = smem_u32(sB + row * SLD + seg);
        CP_ASYNC16(da, A  + (size_t)(m0 + row) * 512 + kt + seg);
        CP_ASYNC16(db, Wt + (size_t)(n0 + row) * 512 + kt + seg);
    }
}

template <int MODE>
__global__ __launch_bounds__(256, 2) void k_mgemm(
    const float* __restrict__ A, const float* __restrict__ Wt,
    float* __restrict__ C, const float* __restrict__ extra)
{
    extern __shared__ float sm[];
    float* sA[3] = { sm, sm + 2 * TILEF, sm + 4 * TILEF };
    float* sB[3] = { sm + TILEF, sm + 3 * TILEF, sm + 5 * TILEF };

    const int tid = threadIdx.x;
    const int m0 = blockIdx.y * 128;
    const int n0 = blockIdx.x * 128;
    const int wid = tid >> 5, lane = tid & 31;
    const int mw = (wid & 3) * 32;
    const int nw = (wid >> 2) * 64;
    const int g = lane >> 2, tig = lane & 3;

    float d[2][8][4];
#pragma unroll
    for (int i = 0; i < 2; ++i)
#pragma unroll
        for (int j = 0; j < 8; ++j)
#pragma unroll
            for (int q = 0; q < 4; ++q) d[i][j][q] = 0.f;

    load_tile_async(A, Wt, m0, n0, 0,  sA[0], sB[0], tid); CP_COMMIT();
    load_tile_async(A, Wt, m0, n0, BK, sA[1], sB[1], tid); CP_COMMIT();

#pragma unroll 1
    for (int t = 0; t < 16; ++t) {
        CP_WAIT1();
        __syncthreads();
        if (t + 2 < 16) {
            int nb = (t + 2) % 3;
            load_tile_async(A, Wt, m0, n0, (t + 2) * BK, sA[nb], sB[nb], tid);
        }
        CP_COMMIT();   // empty group when no load: keeps group accounting uniform
        const float* cA = sA[t % 3];
        const float* cB = sB[t % 3];
#pragma unroll
        for (int kk = 0; kk < 4; ++kk) {
            const int k = kk * 8;
            uint32_t af[2][4], bf[8][2];
#pragma unroll
            for (int i = 0; i < 2; ++i) {
                const float* p = cA + (mw + i * 16 + g) * SLD + k + tig;
                af[i][0] = f2tf32(p[0]);
                af[i][2] = f2tf32(p[4]);
                af[i][1] = f2tf32(p[8 * SLD]);
                af[i][3] = f2tf32(p[8 * SLD + 4]);
            }
#pragma unroll
            for (int j = 0; j < 8; ++j) {
                const float* p = cB + (nw + j * 8 + g) * SLD + k + tig;
                bf[j][0] = f2tf32(p[0]);
                bf[j][1] = f2tf32(p[4]);
            }
#pragma unroll
            for (int i = 0; i < 2; ++i)
#pragma unroll
                for (int j = 0; j < 8; ++j)
                    mma_tf32(d[i][j], af[i], bf[j]);
        }
    }

    if (MODE == 3) {
#pragma unroll
        for (int i = 0; i < 2; ++i) {
#pragma unroll
            for (int half = 0; half < 2; ++half) {
                int m = m0 + mw + i * 16 + g + half * 8;
                int bb = m / HW_;
                int srow = m - bb * HW_;
                int hh = srow / W_;
                int ww = srow - hh * W_;
                const float* crp = extra + (((size_t)(bb * W_ + ww) * H_ + hh) * 512);
                float* outp = C + (size_t)bb * 512 * HW_ + srow;
#pragma unroll
                for (int j = 0; j < 8; ++j) {
                    int nn = n0 + nw + j * 8 + 2 * tig;
                    float v0 = fminf(fmaxf(d[i][j][half * 2 + 0], 0.f), 6.f) + crp[nn];
                    float v1 = fminf(fmaxf(d[i][j][half * 2 + 1], 0.f), 6.f) + crp[nn + 1];
                    outp[(size_t)nn * HW_] = v0;
                    outp[(size_t)(nn + 1) * HW_] = v1;
                }
            }
        }
    } else {
#pragma unroll
        for (int i = 0; i < 2; ++i) {
#pragma unroll
            for (int half = 0; half < 2; ++half) {
                int m = m0 + mw + i * 16 + g + half * 8;
                float* cp = C + (size_t)m * 512;
                const float* ep = (MODE == 1) ? (extra + (size_t)m * 512) : extra;
#pragma unroll
                for (int j = 0; j < 8; ++j) {
                    int nn = n0 + nw + j * 8 + 2 * tig;
                    float v0 = d[i][j][half * 2 + 0];
                    float v1 = d[i][j][half * 2 + 1];
                    if (MODE == 1 || MODE == 2) { v0 += ep[nn]; v1 += ep[nn + 1]; }
                    *(float2*)(cp + nn) = make_float2(v0, v1);
                }
            }
        }
    }
}

// ===========================================================================
// Tensor-core attention. cp.async Q/K loads, f4-coalesced V transpose.
// VLD=102: EVEN (float2 stores stay 8B-aligned) and V-transpose STS stride
// 4*102 mod 32 = 24 -> 8 distinct banks (was 2 at VLD=100).
// ===========================================================================
#define ALD 68
#define VLD 102
#define ATTN_T_SMEM ((2 * 96 * ALD + 64 * VLD) * 4)   // 78336 B

__global__ __launch_bounds__(192, 2) void k_attn_t(
    const float* __restrict__ Q, const float* __restrict__ Kt,
    const float* __restrict__ Vt, float* __restrict__ O)
{
    extern __shared__ float sm[];
    float* sQ = sm;                       // 96 x 68
    float* sK = sm + 96 * ALD;            // 96 x 68
    float* sV = sm + 2 * 96 * ALD;        // 64 x 102 (V^T: [d][key])
    float* sS = sm;                       // 96 x 102 (aliases Q+K region)

    const int tid = threadIdx.x;
    const int n = blockIdx.x >> 3;
    const int hd = blockIdx.x & 7;
    const size_t base = (size_t)n * 96 * 512 + hd * DH;

    // Q,K via cp.async (raw fp32; Q scale folded into fragment cvt below)
    for (int i = tid; i < 96 * 16; i += 192) {
        int r = i >> 4, c4 = (i & 15) * 4;
        CP_ASYNC16(smem_u32(sQ + r * ALD + c4), Q  + base + (size_t)r * 512 + c4);
        CP_ASYNC16(smem_u32(sK + r * ALD + c4), Kt + base + (size_t)r * 512 + c4);
    }
    CP_COMMIT();
    // V transpose: f4 coalesced global read, scalar smem stores
    for (int i = tid; i < 96 * 16; i += 192) {
        int key = i >> 4, d4 = (i & 15) * 4;
        float4 v = *(const float4*)(Vt + base + (size_t)key * 512 + d4);
        sV[(d4 + 0) * VLD + key] = v.x;
        sV[(d4 + 1) * VLD + key] = v.y;
        sV[(d4 + 2) * VLD + key] = v.z;
        sV[(d4 + 3) * VLD + key] = v.w;
    }
    CP_WAIT0();
    __syncthreads();

    const int wid = tid / 32, lane = tid % 32;
    const int g = lane >> 2, tig = lane & 3;
    const int m0 = wid * 16;

    // --- scores: S = (Q/8) K^T ---
    float dS[12][4];
#pragma unroll
    for (int j = 0; j < 12; ++j)
#pragma unroll
        for (int q = 0; q < 4; ++q) dS[j][q] = 0.f;

#pragma unroll
    for (int kk = 0; kk < 8; ++kk) {
        const int k = kk * 8;
        uint32_t a[4];
        const float* pa = sQ + (m0 + g) * ALD + k + tig;
        a[0] = f2tf32(pa[0] * 0.125f);
        a[1] = f2tf32(pa[8 * ALD] * 0.125f);
        a[2] = f2tf32(pa[4] * 0.125f);
        a[3] = f2tf32(pa[8 * ALD + 4] * 0.125f);
#pragma unroll
        for (int j = 0; j < 12; ++j) {
            const float* pb = sK + (j * 8 + g) * ALD + k + tig;
            uint32_t b[2];
            b[0] = f2tf32(pb[0]);
            b[1] = f2tf32(pb[4]);
            mma_tf32(dS[j], a, b);
        }
    }
    __syncthreads();   // all warps done reading Q/K; S may overwrite

#pragma unroll
    for (int j = 0; j < 12; ++j) {
        int col = j * 8 + 2 * tig;
        *(float2*)(sS + (m0 + g) * VLD + col)     = make_float2(dS[j][0], dS[j][1]);
        *(float2*)(sS + (m0 + g + 8) * VLD + col) = make_float2(dS[j][2], dS[j][3]);
    }
    __syncwarp();

    // --- softmax on own 16 rows ---
#pragma unroll 1
    for (int rr = 0; rr < 16; ++rr) {
        float* row = sS + (m0 + rr) * VLD;
        float v0 = row[lane], v1 = row[lane + 32], v2 = row[lane + 64];
        float mx = fmaxf(v0, fmaxf(v1, v2));
#pragma unroll
        for (int o = 16; o > 0; o >>= 1)
            mx = fmaxf(mx, __shfl_xor_sync(0xffffffffu, mx, o));
        float e0 = __expf(v0 - mx), e1 = __expf(v1 - mx), e2 = __expf(v2 - mx);
        float s = e0 + e1 + e2;
#pragma unroll
        for (int o = 16; o > 0; o >>= 1)
            s += __shfl_xor_sync(0xffffffffu, s, o);
        float inv = 1.f / s;
        row[lane] = e0 * inv; row[lane + 32] = e1 * inv; row[lane + 64] = e2 * inv;
    }
    __syncwarp();

    // --- PV ---
    float dO[8][4];
#pragma unroll
    for (int j = 0; j < 8; ++j)
#pragma unroll
        for (int q = 0; q < 4; ++q) dO[j][q] = 0.f;

#pragma unroll
    for (int kk = 0; kk < 12; ++kk) {
        const int k = kk * 8;
        uint32_t a[4];
        const float* pa = sS + (m0 + g) * VLD + k + tig;
        a[0] = f2tf32(pa[0]);
        a[1] = f2tf32(pa[8 * VLD]);
        a[2] = f2tf32(pa[4]);
        a[3] = f2tf32(pa[8 * VLD + 4]);
#pragma unroll
        for (int j = 0; j < 8; ++j) {
            const float* pb = sV + (j * 8 + g) * VLD + k + tig;
            uint32_t b[2];
            b[0] = f2tf32(pb[0]);
            b[1] = f2tf32(pb[4]);
            mma_tf32(dO[j], a, b);
        }
    }

#pragma unroll
    for (int j = 0; j < 8; ++j) {
        int col = j * 8 + 2 * tig;
        *(float2*)(O + base + (size_t)(m0 + g) * 512 + col)     = make_float2(dO[j][0], dO[j][1]);
        *(float2*)(O + base + (size_t)(m0 + g + 8) * 512 + col) = make_float2(dO[j][2], dO[j][3]);
    }
}

// ===========================================================================
// Depthwise 3x3 + BN (eval) -> token-major [tok, 512]
// grid (36, 512, 8): c,b from grid dims; per-block broadcast of taps + BN.
// ===========================================================================
__global__ __launch_bounds__(256) void k_dwconv(
    const float* __restrict__ x, const float* __restrict__ wgt,
    const float* __restrict__ bg, const float* __restrict__ bb_,
    const float* __restrict__ bm, const float* __restrict__ bv,
    float* __restrict__ y)
{
    __shared__ float sp[12];   // 9 taps, sc, bm, bb
    const int tid = threadIdx.x;
    const int c = blockIdx.y, b = blockIdx.z;
    if (tid < 9)        sp[tid] = wgt[c * 9 + tid];
    else if (tid == 9)  sp[9]  = bg[c] * rsqrtf(bv[c] + 1e-5f);
    else if (tid == 10) sp[10] = bm[c];
    else if (tid == 11) sp[11] = bb_[c];
    __syncthreads();

    const int s = blockIdx.x * 256 + tid;       // 0..9215
    const int h = s / W_, w = s - (s / W_) * W_;
    const float* xc = x + ((size_t)b * C_ + c) * HW_;

    float acc = 0.f;
#pragma unroll
    for (int kh = 0; kh < 3; ++kh) {
        int hh = h + kh - 1;
        if (hh < 0 || hh >= H_) continue;
#pragma unroll
        for (int kw = 0; kw < 3; ++kw) {
            int ww = w + kw - 1;
            if (ww < 0 || ww >= W_) continue;
            acc = fmaf(xc[hh * W_ + ww], sp[kh * 3 + kw], acc);
        }
    }
    float v = (acc - sp[10]) * sp[9] + sp[11];
    y[((size_t)b * HW_ + s) * 512 + c] = v;
}

// ===========================================================================
// Launch
// ===========================================================================
extern "C" void kernel_launch(void* const* d_in, const int* in_sizes, int n_in,
                              void* d_out, int out_size)
{
    const float* x      = (const float*)d_in[0];
    const float* msa_Wk = (const float*)d_in[1];
    const float* msa_Wv = (const float*)d_in[2];
    const float* msa_Wo = (const float*)d_in[3];
    const float* cr_Wq  = (const float*)d_in[4];
    const float* cr_bq  = (const float*)d_in[5];
    const float* cr_Wv  = (const float*)d_in[6];
    const float* cr_Wo  = (const float*)d_in[7];
    const float* dw_w   = (const float*)d_in[8];
    const float* bn_g   = (const float*)d_in[9];
    const float* bn_b   = (const float*)d_in[10];
    const float* bn_m   = (const float*)d_in[11];
    const float* bn_v   = (const float*)d_in[12];
    const float* pw_w   = (const float*)d_in[13];
    float* out = (float*)d_out;

    float *vqk, *bA, *bB, *bC;
    cudaGetSymbolAddress((void**)&vqk, g_vqk);
    cudaGetSymbolAddress((void**)&bA, g_bA);
    cudaGetSymbolAddress((void**)&bB, g_bB);
    cudaGetSymbolAddress((void**)&bC, g_bC);

    cudaFuncSetAttribute(k_attn_t, cudaFuncAttributeMaxDynamicSharedMemorySize, ATTN_T_SMEM);
    cudaFuncSetAttribute(k_mgemm<0>, cudaFuncAttributeMaxDynamicSharedMemorySize, GSMEM);
    cudaFuncSetAttribute(k_mgemm<1>, cudaFuncAttributeMaxDynamicSharedMemorySize, GSMEM);
    cudaFuncSetAttribute(k_mgemm<2>, cudaFuncAttributeMaxDynamicSharedMemorySize, GSMEM);
    cudaFuncSetAttribute(k_mgemm<3>, cudaFuncAttributeMaxDynamicSharedMemorySize, GSMEM);

    dim3 tgrid(3, 16, B_ * H_), tblk(32, 8);
    dim3 ggrid(4, NTOK / 128), gblk(256);
    dim3 dgrid(HW_ / 256, C_, B_);

    // 1. vqk = permute(x)
    k_bchw_to_nhc<<<tgrid, tblk>>>(x, vqk);
    // 2. K = vqk@Wk^T + vqk
    k_mgemm<1><<<ggrid, gblk, GSMEM>>>(vqk, msa_Wk, bA, vqk);
    // 3. V = vqk@Wv^T
    k_mgemm<0><<<ggrid, gblk, GSMEM>>>(vqk, msa_Wv, bB, nullptr);
    // 4. attn(vqk, K, V) -> bC
    k_attn_t<<<B_ * W_ * NHEAD, 192, ATTN_T_SMEM>>>(vqk, bA, bB, bC);
    // 5. O = attn@Wo^T -> bA
    k_mgemm<0><<<ggrid, gblk, GSMEM>>>(bC, msa_Wo, bA, nullptr);
    // 6. q_view = nhc_to_bchw(O) -> bB
    k_nhc_to_bchw<<<tgrid, tblk>>>(bA, bB);
    // 7. Q2 = q_view@Wq^T + bq -> bC
    k_mgemm<2><<<ggrid, gblk, GSMEM>>>(bB, cr_Wq, bC, cr_bq);
    // 8. KV = vqk@crWv^T -> bA
    k_mgemm<0><<<ggrid, gblk, GSMEM>>>(vqk, cr_Wv, bA, nullptr);
    // 9. attn(Q2, KV, KV) -> bB
    k_attn_t<<<B_ * W_ * NHEAD, 192, ATTN_T_SMEM>>>(bC, bA, bA, bB);
    // 10. CR = crattn@crWo^T -> bC
    k_mgemm<0><<<ggrid, gblk, GSMEM>>>(bB, cr_Wo, bC, nullptr);
    // 11. depthwise+BN -> bA (token-major)
    k_dwconv<<<dgrid, 256>>>(x, dw_w, bn_g, bn_b, bn_m, bn_v, bA);
    // 12. out = clip(bA@pw^T,0,6) + permute(CR) -> BCHW
    k_mgemm<3><<<ggrid, gblk, GSMEM>>>(bA, pw_w, out, bC);
}

// round 8
// speedup vs baseline: 4.4849x; 1.7703x over previous
#include <cuda_runtime.h>
#include <cuda_fp16.h>
#include <cstdint>
#include <string.h>
#include <math.h>

#define B_    8
#define C_    512
#define H_    96
#define W_    96
#define HW_   9216
#define NTOK  73728
#define IMGN  37748736
#define NHEAD 8
#define DH    64

// Scratch buffers
__device__ float  g_f32[IMGN];              // vqk fp32 (residual), later CR fp32
__device__ __half g_hv[IMGN];               // vqk half
__device__ __half g_hA[IMGN];
__device__ __half g_hB[IMGN];
__device__ __half g_hC[IMGN];
__device__ __half g_hD[IMGN];
__device__ __half g_wh[7 * C_ * C_];        // converted weights

// ===========================================================================
// PTX helpers (non-'a' features only: cp.async, ldmatrix, mma.sync sm_80)
// ===========================================================================
__device__ __forceinline__ uint32_t smem_u32(const void* p) {
    uint32_t a;
    asm("{ .reg .u64 t; cvta.to.shared.u64 t, %1; cvt.u32.u64 %0, t; }"
        : "=r"(a) : "l"(p));
    return a;
}
#define CP_ASYNC16(dst, src) \
    asm volatile("cp.async.cg.shared.global [%0], [%1], 16;" :: "r"(dst), "l"(src))
#define CP_COMMIT() asm volatile("cp.async.commit_group;" ::: "memory")
#define CP_WAIT0()  asm volatile("cp.async.wait_group 0;" ::: "memory")
#define CP_WAIT1()  asm volatile("cp.async.wait_group 1;" ::: "memory")

#define LDSM_X4(r0, r1, r2, r3, addr) \
    asm volatile("ldmatrix.sync.aligned.m8n8.x4.shared.b16 {%0,%1,%2,%3}, [%4];" \
        : "=r"(r0), "=r"(r1), "=r"(r2), "=r"(r3) : "r"(addr))

__device__ __forceinline__ void mma_f16(float* d, const uint32_t* a, const uint32_t* b) {
    asm volatile(
        "mma.sync.aligned.m16n8k16.row.col.f32.f16.f16.f32 "
        "{%0,%1,%2,%3}, {%4,%5,%6,%7}, {%8,%9}, {%0,%1,%2,%3};"
        : "+f"(d[0]), "+f"(d[1]), "+f"(d[2]), "+f"(d[3])
        : "r"(a[0]), "r"(a[1]), "r"(a[2]), "r"(a[3]), "r"(b[0]), "r"(b[1]));
}

__device__ __forceinline__ uint32_t pack2h(float x, float y) {
    __half2 h = __floats2half2_rn(x, y);
    uint32_t u;
    memcpy(&u, &h, 4);
    return u;
}

// ===========================================================================
// Weight fp32 -> fp16
// ===========================================================================
__global__ void k_w2h(const float* __restrict__ w, __half* __restrict__ o, int n) {
    int i = blockIdx.x * 256 + threadIdx.x;
    if (i < n) o[i] = __float2half(w[i]);
}

// ===========================================================================
// Transpose bchw -> nhc, dual write (fp32 + half)
// ===========================================================================
__global__ void k_bchw_to_nhc(const float* __restrict__ src,
                              float* __restrict__ dst, __half* __restrict__ dsth) {
    __shared__ float tile[32][33];
    int bh = blockIdx.z;
    int b = bh / H_, h = bh % H_;
    int c0 = blockIdx.y * 32;
    int w0 = blockIdx.x * 32;
    int tx = threadIdx.x, ty = threadIdx.y;
#pragma unroll
    for (int k = 0; k < 4; ++k) {
        int c = c0 + ty + k * 8;
        tile[ty + k * 8][tx] = src[(((size_t)b * C_ + c) * H_ + h) * W_ + w0 + tx];
    }
    __syncthreads();
#pragma unroll
    for (int k = 0; k < 4; ++k) {
        int w = w0 + ty + k * 8;
        size_t di = (((size_t)b * W_ + w) * H_ + h) * C_ + c0 + tx;
        float v = tile[tx][ty + k * 8];
        dst[di] = v;
        dsth[di] = __float2half(v);
    }
}

// ===========================================================================
// fp16 mma GEMM: C = A @ W^T. A:[M,512]h, W:[512,512]h (row n, k contiguous).
// CTA 128x128, BK=64 halves, 3-stage cp.async, ldmatrix frags.
// MODE 0: ->half   1: +extra32[m,n] ->half   2: +bias32[n] ->half
// MODE 4: scatter nhc->bchw ->half (fused transpose; m is NHC token!)
// MODE 5: ->fp32   3: relu6 + cr32 gather -> fp32 BCHW scatter
// ===========================================================================
#define BKH    64
#define SLDH   72                       // halves per smem row (144 B)
#define TILEH  (128 * SLDH)             // halves per operand tile
#define STAGEB (2 * TILEH * 2)          // bytes per stage (A+B)
#define GSMEM  (3 * STAGEB)             // 110592 B

__device__ __forceinline__ void load_tile_h(
    const __half* __restrict__ A, const __half* __restrict__ Wt,
    int m0, int n0, int kt, uint32_t sa, uint32_t sb, int tid)
{
#pragma unroll
    for (int it = 0; it < 4; ++it) {
        int c = it * 256 + tid;          // 0..1023
        int row = c >> 3;
        int seg = c & 7;                 // 16B = 8 halves
        CP_ASYNC16(sa + (row * SLDH + seg * 8) * 2,
                   A + (size_t)(m0 + row) * 512 + kt + seg * 8);
        CP_ASYNC16(sb + (row * SLDH + seg * 8) * 2,
                   Wt + (size_t)(n0 + row) * 512 + kt + seg * 8);
    }
}

template <int MODE>
__global__ __launch_bounds__(256, 2) void k_hgemm(
    const __half* __restrict__ A, const __half* __restrict__ Wt,
    void* __restrict__ Cv, const float* __restrict__ extra)
{
    extern __shared__ char smraw[];
    const uint32_t s0 = smem_u32(smraw);

    const int tid = threadIdx.x;
    const int m0 = blockIdx.y * 128;
    const int n0 = blockIdx.x * 128;
    const int wid = tid >> 5, lane = tid & 31;
    const int mw = (wid & 3) * 32;
    const int nw = (wid >> 2) * 64;
    const int g = lane >> 2, tig = lane & 3;

    // ldmatrix lane addresses (byte offsets within a stage)
    uint32_t aoff[2], boff[4];
#pragma unroll
    for (int i = 0; i < 2; ++i)
        aoff[i] = ((mw + i * 16 + (lane & 15)) * SLDH + (lane >> 4) * 8) * 2;
#pragma unroll
    for (int jp = 0; jp < 4; ++jp)
        boff[jp] = (uint32_t)(TILEH * 2) +
                   ((nw + jp * 16 + ((lane & 7) | ((lane >> 4) << 3))) * SLDH +
                    ((lane >> 3) & 1) * 8) * 2;

    float d[2][8][4];
#pragma unroll
    for (int i = 0; i < 2; ++i)
#pragma unroll
        for (int j = 0; j < 8; ++j)
#pragma unroll
            for (int q = 0; q < 4; ++q) d[i][j][q] = 0.f;

    load_tile_h(A, Wt, m0, n0, 0,    s0,          s0 + TILEH * 2,          tid); CP_COMMIT();
    load_tile_h(A, Wt, m0, n0, BKH,  s0 + STAGEB, s0 + STAGEB + TILEH * 2, tid); CP_COMMIT();

#pragma unroll 1
    for (int t = 0; t < 8; ++t) {
        CP_WAIT1();
        __syncthreads();
        if (t + 2 < 8) {
            uint32_t sb = s0 + ((t + 2) % 3) * STAGEB;
            load_tile_h(A, Wt, m0, n0, (t + 2) * BKH, sb, sb + TILEH * 2, tid);
        }
        CP_COMMIT();
        const uint32_t st = s0 + (t % 3) * STAGEB;
#pragma unroll
        for (int kk = 0; kk < 4; ++kk) {
            const uint32_t kb = kk * 32;      // 16 halves
            uint32_t af[2][4], bf[8][2];
#pragma unroll
            for (int i = 0; i < 2; ++i)
                LDSM_X4(af[i][0], af[i][1], af[i][2], af[i][3], st + aoff[i] + kb);
#pragma unroll
            for (int jp = 0; jp < 4; ++jp)
                LDSM_X4(bf[2 * jp][0], bf[2 * jp][1], bf[2 * jp + 1][0], bf[2 * jp + 1][1],
                        st + boff[jp] + kb);
#pragma unroll
            for (int i = 0; i < 2; ++i)
#pragma unroll
                for (int j = 0; j < 8; ++j)
                    mma_f16(d[i][j], af[i], bf[j]);
        }
    }

    // Epilogue (c-frag: c0:(g,2tig) c1:(g,2tig+1) c2:(g+8,2tig) c3:(g+8,2tig+1))
#pragma unroll
    for (int i = 0; i < 2; ++i) {
#pragma unroll
        for (int half_ = 0; half_ < 2; ++half_) {
            int m = m0 + mw + i * 16 + g + half_ * 8;
            if (MODE == 3 || MODE == 4) {
                int bb = m / HW_;
                int srow = m - bb * HW_;
                int p = srow / W_;          // MODE3: h ; MODE4: w (nhc token!)
                int q = srow - p * W_;      // MODE3: w ; MODE4: h
                if (MODE == 3) {
                    const float* crp = extra + (((size_t)(bb * W_ + q) * H_ + p) * 512);
                    float* outp = (float*)Cv + (size_t)bb * 512 * HW_ + srow;
#pragma unroll
                    for (int j = 0; j < 8; ++j) {
                        int nn = n0 + nw + j * 8 + 2 * tig;
                        float v0 = fminf(fmaxf(d[i][j][half_ * 2 + 0], 0.f), 6.f) + crp[nn];
                        float v1 = fminf(fmaxf(d[i][j][half_ * 2 + 1], 0.f), 6.f) + crp[nn + 1];
                        outp[(size_t)nn * HW_] = v0;
                        outp[(size_t)(nn + 1) * HW_] = v1;
                    }
                } else {
                    // MODE 4: m = b*9216 + w*96 + h  -> write bchw at h*96 + w = q*96 + p
                    __half* outp = (__half*)Cv + (size_t)bb * 512 * HW_ + q * W_ + p;
#pragma unroll
                    for (int j = 0; j < 8; ++j) {
                        int nn = n0 + nw + j * 8 + 2 * tig;
                        outp[(size_t)nn * HW_] = __float2half(d[i][j][half_ * 2 + 0]);
                        outp[(size_t)(nn + 1) * HW_] = __float2half(d[i][j][half_ * 2 + 1]);
                    }
                }
            } else if (MODE == 5) {
                float* cp = (float*)Cv + (size_t)m * 512;
#pragma unroll
                for (int j = 0; j < 8; ++j) {
                    int nn = n0 + nw + j * 8 + 2 * tig;
                    *(float2*)(cp + nn) =
                        make_float2(d[i][j][half_ * 2 + 0], d[i][j][half_ * 2 + 1]);
                }
            } else {
                __half* cp = (__half*)Cv + (size_t)m * 512;
                const float* ep = (MODE == 1) ? (extra + (size_t)m * 512) : extra;
#pragma unroll
                for (int j = 0; j < 8; ++j) {
                    int nn = n0 + nw + j * 8 + 2 * tig;
                    float v0 = d[i][j][half_ * 2 + 0];
                    float v1 = d[i][j][half_ * 2 + 1];
                    if (MODE == 1 || MODE == 2) { v0 += ep[nn]; v1 += ep[nn + 1]; }
                    *(uint32_t*)(cp + nn) = pack2h(v0, v1);
                }
            }
        }
    }
}

// ===========================================================================
// Flash-style fp16 attention: 6 warps, warp = 16 query rows.
// QK^T (mma) -> register softmax (quad shfl) -> P regs ARE the PV A-frags
// -> PV (mma, V^T in smem). Only one __syncthreads.
// ===========================================================================
#define AQLD 72     // sQ/sK halves stride (144 B)
#define AVLD 104    // sVt halves stride (208 B)
#define ATTN_SMEM ((2 * 96 * AQLD + 64 * AVLD) * 2)   // 40960 B

__global__ __launch_bounds__(192, 3) void k_attn_h(
    const __half* __restrict__ Q, const __half* __restrict__ Kt,
    const __half* __restrict__ Vt, __half* __restrict__ O)
{
    extern __shared__ char smraw[];
    const uint32_t sQ = smem_u32(smraw);
    const uint32_t sK = sQ + 96 * AQLD * 2;
    const uint32_t sV = sK + 96 * AQLD * 2;
    __half* sVh = (__half*)(smraw + 2 * 96 * AQLD * 2);

    const int tid = threadIdx.x;
    const int n = blockIdx.x >> 3;
    const int hd = blockIdx.x & 7;
    const size_t base = (size_t)n * 96 * 512 + hd * DH;

    // Q, K via cp.async (16B = 8 halves)
    for (int i = tid; i < 96 * 8; i += 192) {
        int r = i >> 3, seg = i & 7;
        CP_ASYNC16(sQ + (r * AQLD + seg * 8) * 2, Q  + base + (size_t)r * 512 + seg * 8);
        CP_ASYNC16(sK + (r * AQLD + seg * 8) * 2, Kt + base + (size_t)r * 512 + seg * 8);
    }
    CP_COMMIT();
    // V transpose: [key][d] -> sVt[d][key]
    for (int i = tid; i < 96 * 8; i += 192) {
        int key = i >> 3, d8 = (i & 7) * 8;
        uint4 v = *(const uint4*)(Vt + base + (size_t)key * 512 + d8);
        __half2 hh[4];
        memcpy(hh, &v, 16);
#pragma unroll
        for (int q = 0; q < 4; ++q) {
            sVh[(d8 + 2 * q) * AVLD + key]     = __low2half(hh[q]);
            sVh[(d8 + 2 * q + 1) * AVLD + key] = __high2half(hh[q]);
        }
    }
    CP_WAIT0();
    __syncthreads();

    const int wid = tid / 32, lane = tid % 32;
    const int g = lane >> 2, tig = lane & 3;
    const int m0 = wid * 16;

    const uint32_t aAddr = sQ + ((m0 + (lane & 15)) * AQLD + (lane >> 4) * 8) * 2;
    const uint32_t bRow = (lane & 7) | ((lane >> 4) << 3);
    const uint32_t bCol = ((lane >> 3) & 1) * 8;

    // --- QK^T: dS[12][4] over 4 k-steps ---
    float dS[12][4];
#pragma unroll
    for (int j = 0; j < 12; ++j)
#pragma unroll
        for (int q = 0; q < 4; ++q) dS[j][q] = 0.f;

#pragma unroll
    for (int kk = 0; kk < 4; ++kk) {
        uint32_t af[4];
        LDSM_X4(af[0], af[1], af[2], af[3], aAddr + kk * 32);
#pragma unroll
        for (int jp = 0; jp < 6; ++jp) {
            uint32_t b0, b1, b2, b3;
            LDSM_X4(b0, b1, b2, b3,
                    sK + ((jp * 16 + bRow) * AQLD + bCol) * 2 + kk * 32);
            uint32_t bA[2] = {b0, b1}, bB[2] = {b2, b3};
            mma_f16(dS[2 * jp], af, bA);
            mma_f16(dS[2 * jp + 1], af, bB);
        }
    }

    // --- register softmax over 96 cols (rows g and g+8 within quad) ---
    float mx0 = -1e30f, mx1 = -1e30f;
#pragma unroll
    for (int j = 0; j < 12; ++j) {
        dS[j][0] *= 0.125f; dS[j][1] *= 0.125f;
        dS[j][2] *= 0.125f; dS[j][3] *= 0.125f;
        mx0 = fmaxf(mx0, fmaxf(dS[j][0], dS[j][1]));
        mx1 = fmaxf(mx1, fmaxf(dS[j][2], dS[j][3]));
    }
    mx0 = fmaxf(mx0, __shfl_xor_sync(0xffffffffu, mx0, 1));
    mx0 = fmaxf(mx0, __shfl_xor_sync(0xffffffffu, mx0, 2));
    mx1 = fmaxf(mx1, __shfl_xor_sync(0xffffffffu, mx1, 1));
    mx1 = fmaxf(mx1, __shfl_xor_sync(0xffffffffu, mx1, 2));
    float s0 = 0.f, s1 = 0.f;
#pragma unroll
    for (int j = 0; j < 12; ++j) {
        dS[j][0] = __expf(dS[j][0] - mx0); dS[j][1] = __expf(dS[j][1] - mx0);
        dS[j][2] = __expf(dS[j][2] - mx1); dS[j][3] = __expf(dS[j][3] - mx1);
        s0 += dS[j][0] + dS[j][1];
        s1 += dS[j][2] + dS[j][3];
    }
    s0 += __shfl_xor_sync(0xffffffffu, s0, 1);
    s0 += __shfl_xor_sync(0xffffffffu, s0, 2);
    s1 += __shfl_xor_sync(0xffffffffu, s1, 1);
    s1 += __shfl_xor_sync(0xffffffffu, s1, 2);
    const float i0 = 1.f / s0, i1 = 1.f / s1;

    // pack P into PV A-frags (C-frag layout == A-frag layout)
    uint32_t aP[6][4];
#pragma unroll
    for (int kk = 0; kk < 6; ++kk) {
        aP[kk][0] = pack2h(dS[2 * kk][0] * i0, dS[2 * kk][1] * i0);
        aP[kk][1] = pack2h(dS[2 * kk][2] * i1, dS[2 * kk][3] * i1);
        aP[kk][2] = pack2h(dS[2 * kk + 1][0] * i0, dS[2 * kk + 1][1] * i0);
        aP[kk][3] = pack2h(dS[2 * kk + 1][2] * i1, dS[2 * kk + 1][3] * i1);
    }

    // --- PV: dO[8][4], K-dim = 96 keys (6 steps), N = 64 d ---
    float dO[8][4];
#pragma unroll
    for (int j = 0; j < 8; ++j)
#pragma unroll
        for (int q = 0; q < 4; ++q) dO[j][q] = 0.f;

#pragma unroll
    for (int kk = 0; kk < 6; ++kk) {
        uint32_t bf[8][2];
#pragma unroll
        for (int jp = 0; jp < 4; ++jp)
            LDSM_X4(bf[2 * jp][0], bf[2 * jp][1], bf[2 * jp + 1][0], bf[2 * jp + 1][1],
                    sV + ((jp * 16 + bRow) * AVLD + bCol) * 2 + kk * 32);
#pragma unroll
        for (int j = 0; j < 8; ++j)
            mma_f16(dO[j], aP[kk], bf[j]);
    }

#pragma unroll
    for (int j = 0; j < 8; ++j) {
        int col = j * 8 + 2 * tig;
        *(uint32_t*)(O + base + (size_t)(m0 + g) * 512 + col) =
            pack2h(dO[j][0], dO[j][1]);
        *(uint32_t*)(O + base + (size_t)(m0 + g + 8) * 512 + col) =
            pack2h(dO[j][2], dO[j][3]);
    }
}

// ===========================================================================
// Depthwise 3x3 + BN -> token-major half [tok, 512]
// ===========================================================================
__global__ __launch_bounds__(256) void k_dwconv(
    const float* __restrict__ x, const float* __restrict__ wgt,
    const float* __restrict__ bg, const float* __restrict__ bb_,
    const float* __restrict__ bm, const float* __restrict__ bv,
    __half* __restrict__ y)
{
    __shared__ float sp[12];
    const int tid = threadIdx.x;
    const int c = blockIdx.y, b = blockIdx.z;
    if (tid < 9)        sp[tid] = wgt[c * 9 + tid];
    else if (tid == 9)  sp[9]  = bg[c] * rsqrtf(bv[c] + 1e-5f);
    else if (tid == 10) sp[10] = bm[c];
    else if (tid == 11) sp[11] = bb_[c];
    __syncthreads();

    const int s = blockIdx.x * 256 + tid;
    const int h = s / W_, w = s - (s / W_) * W_;
    const float* xc = x + ((size_t)b * C_ + c) * HW_;

    float acc = 0.f;
#pragma unroll
    for (int kh = 0; kh < 3; ++kh) {
        int hh = h + kh - 1;
        if (hh < 0 || hh >= H_) continue;
#pragma unroll
        for (int kw = 0; kw < 3; ++kw) {
            int ww = w + kw - 1;
            if (ww < 0 || ww >= W_) continue;
            acc = fmaf(xc[hh * W_ + ww], sp[kh * 3 + kw], acc);
        }
    }
    float v = (acc - sp[10]) * sp[9] + sp[11];
    y[((size_t)b * HW_ + s) * 512 + c] = __float2half(v);
}

// ===========================================================================
// Launch
// ===========================================================================
extern "C" void kernel_launch(void* const* d_in, const int* in_sizes, int n_in,
                              void* d_out, int out_size)
{
    const float* x      = (const float*)d_in[0];
    const float* msa_Wk = (const float*)d_in[1];
    const float* msa_Wv = (const float*)d_in[2];
    const float* msa_Wo = (const float*)d_in[3];
    const float* cr_Wq  = (const float*)d_in[4];
    const float* cr_bq  = (const float*)d_in[5];
    const float* cr_Wv  = (const float*)d_in[6];
    const float* cr_Wo  = (const float*)d_in[7];
    const float* dw_w   = (const float*)d_in[8];
    const float* bn_g   = (const float*)d_in[9];
    const float* bn_b   = (const float*)d_in[10];
    const float* bn_m   = (const float*)d_in[11];
    const float* bn_v   = (const float*)d_in[12];
    const float* pw_w   = (const float*)d_in[13];
    float* out = (float*)d_out;

    float* f32;  __half *hv, *hA, *hB, *hC, *hD, *wh;
    cudaGetSymbolAddress((void**)&f32, g_f32);
    cudaGetSymbolAddress((void**)&hv, g_hv);
    cudaGetSymbolAddress((void**)&hA, g_hA);
    cudaGetSymbolAddress((void**)&hB, g_hB);
    cudaGetSymbolAddress((void**)&hC, g_hC);
    cudaGetSymbolAddress((void**)&hD, g_hD);
    cudaGetSymbolAddress((void**)&wh, g_wh);

    cudaFuncSetAttribute(k_hgemm<0>, cudaFuncAttributeMaxDynamicSharedMemorySize, GSMEM);
    cudaFuncSetAttribute(k_hgemm<1>, cudaFuncAttributeMaxDynamicSharedMemorySize, GSMEM);
    cudaFuncSetAttribute(k_hgemm<2>, cudaFuncAttributeMaxDynamicSharedMemorySize, GSMEM);
    cudaFuncSetAttribute(k_hgemm<3>, cudaFuncAttributeMaxDynamicSharedMemorySize, GSMEM);
    cudaFuncSetAttribute(k_hgemm<4>, cudaFuncAttributeMaxDynamicSharedMemorySize, GSMEM);
    cudaFuncSetAttribute(k_hgemm<5>, cudaFuncAttributeMaxDynamicSharedMemorySize, GSMEM);

    const int WN = C_ * C_;
    const int wgrid = (WN + 255) / 256;
    // 0. weights -> half  [Wk, Wv, Wo, crWq, crWv, crWo, pw]
    k_w2h<<<wgrid, 256>>>(msa_Wk, wh + 0 * WN, WN);
    k_w2h<<<wgrid, 256>>>(msa_Wv, wh + 1 * WN, WN);
    k_w2h<<<wgrid, 256>>>(msa_Wo, wh + 2 * WN, WN);
    k_w2h<<<wgrid, 256>>>(cr_Wq,  wh + 3 * WN, WN);
    k_w2h<<<wgrid, 256>>>(cr_Wv,  wh + 4 * WN, WN);
    k_w2h<<<wgrid, 256>>>(cr_Wo,  wh + 5 * WN, WN);
    k_w2h<<<wgrid, 256>>>(pw_w,   wh + 6 * WN, WN);

    dim3 tgrid(3, 16, B_ * H_), tblk(32, 8);
    dim3 ggrid(4, NTOK / 128), gblk(256);
    dim3 dgrid(HW_ / 256, C_, B_);

    // 1. vqk = permute(x)  (fp32 + half)
    k_bchw_to_nhc<<<tgrid, tblk>>>(x, f32, hv);
    // 2. K = vqk@Wk^T + vqk -> hA
    k_hgemm<1><<<ggrid, gblk, GSMEM>>>(hv, wh + 0 * WN, hA, f32);
    // 3. V = vqk@Wv^T -> hB
    k_hgemm<0><<<ggrid, gblk, GSMEM>>>(hv, wh + 1 * WN, hB, nullptr);
    // 4. attn(vqk, K, V) -> hC
    k_attn_h<<<B_ * W_ * NHEAD, 192, ATTN_SMEM>>>(hv, hA, hB, hC);
    // 5. O = attn@Wo^T, fused nhc->bchw scatter -> hD (= q_view)
    k_hgemm<4><<<ggrid, gblk, GSMEM>>>(hC, wh + 2 * WN, hD, nullptr);
    // 7. Q2 = q_view@Wq^T + bq -> hC
    k_hgemm<2><<<ggrid, gblk, GSMEM>>>(hD, wh + 3 * WN, hC, cr_bq);
    // 8. KV = vqk@crWv^T -> hA
    k_hgemm<0><<<ggrid, gblk, GSMEM>>>(hv, wh + 4 * WN, hA, nullptr);
    // 9. attn(Q2, KV, KV) -> hB
    k_attn_h<<<B_ * W_ * NHEAD, 192, ATTN_SMEM>>>(hC, hA, hA, hB);
    // 10. CR = crattn@crWo^T -> f32 (vqk32 dead; reuse)
    k_hgemm<5><<<ggrid, gblk, GSMEM>>>(hB, wh + 5 * WN, f32, nullptr);
    // 11. depthwise+BN -> hD (half, token-major)
    k_dwconv<<<dgrid, 256>>>(x, dw_w, bn_g, bn_b, bn_m, bn_v, hD);
    // 12. out = clip(hD@pw^T,0,6) + permute(CR) -> BCHW fp32
    k_hgemm<3><<<ggrid, gblk, GSMEM>>>(hD, wh + 6 * WN, out, f32);
}

// round 9
// speedup vs baseline: 4.9229x; 1.0977x over previous
#include <cuda_runtime.h>
#include <cuda_fp16.h>
#include <cstdint>
#include <string.h>
#include <math.h>

#define B_    8
#define C_    512
#define H_    96
#define W_    96
#define HW_   9216
#define NTOK  73728
#define IMGN  37748736
#define NHEAD 8
#define DH    64
#define WN    262144          // C_*C_ = 2^18

// Scratch buffers
__device__ float  g_f32[IMGN];              // CR fp32
__device__ __half g_hv[IMGN];               // vqk half
__device__ __half g_hA[IMGN];
__device__ __half g_hB[IMGN];
__device__ __half g_hC[IMGN];
__device__ __half g_hD[IMGN];
__device__ __half g_hE[IMGN];
__device__ __half g_wh[7 * WN];             // packed half weights

// ===========================================================================
// PTX helpers
// ===========================================================================
__device__ __forceinline__ uint32_t smem_u32(const void* p) {
    uint32_t a;
    asm("{ .reg .u64 t; cvta.to.shared.u64 t, %1; cvt.u32.u64 %0, t; }"
        : "=r"(a) : "l"(p));
    return a;
}
#define CP_ASYNC16(dst, src) \
    asm volatile("cp.async.cg.shared.global [%0], [%1], 16;" :: "r"(dst), "l"(src))
#define CP_COMMIT() asm volatile("cp.async.commit_group;" ::: "memory")
#define CP_WAIT0()  asm volatile("cp.async.wait_group 0;" ::: "memory")
#define CP_WAIT1()  asm volatile("cp.async.wait_group 1;" ::: "memory")

#define LDSM_X4(r0, r1, r2, r3, addr) \
    asm volatile("ldmatrix.sync.aligned.m8n8.x4.shared.b16 {%0,%1,%2,%3}, [%4];" \
        : "=r"(r0), "=r"(r1), "=r"(r2), "=r"(r3) : "r"(addr))

__device__ __forceinline__ void mma_f16(float* d, const uint32_t* a, const uint32_t* b) {
    asm volatile(
        "mma.sync.aligned.m16n8k16.row.col.f32.f16.f16.f32 "
        "{%0,%1,%2,%3}, {%4,%5,%6,%7}, {%8,%9}, {%0,%1,%2,%3};"
        : "+f"(d[0]), "+f"(d[1]), "+f"(d[2]), "+f"(d[3])
        : "r"(a[0]), "r"(a[1]), "r"(a[2]), "r"(a[3]), "r"(b[0]), "r"(b[1]));
}

__device__ __forceinline__ uint32_t pack2h(float x, float y) {
    __half2 h = __floats2half2_rn(x, y);
    uint32_t u;
    memcpy(&u, &h, 4);
    return u;
}

// ===========================================================================
// All weights fp32 -> fp16 in ONE launch.
// Slot order: 0=Wk 1=Wv 2=crWv (contiguous: the fused N=1536 GEMM B operand)
//             3=Wo 4=crWq 5=crWo 6=pw
// ===========================================================================
__global__ void k_w2h_all(const float* __restrict__ wk, const float* __restrict__ wv,
                          const float* __restrict__ cwv, const float* __restrict__ wo,
                          const float* __restrict__ cwq, const float* __restrict__ cwo,
                          const float* __restrict__ pw, __half* __restrict__ o) {
    int i = blockIdx.x * 256 + threadIdx.x;
    if (i >= 7 * WN) return;
    int slot = i >> 18, off = i & (WN - 1);
    const float* src;
    switch (slot) {
        case 0: src = wk;  break;
        case 1: src = wv;  break;
        case 2: src = cwv; break;
        case 3: src = wo;  break;
        case 4: src = cwq; break;
        case 5: src = cwo; break;
        default: src = pw; break;
    }
    o[i] = __float2half(src[off]);
}

// ===========================================================================
// Transpose bchw -> nhc (half only)
// ===========================================================================
__global__ void k_bchw_to_nhc(const float* __restrict__ src, __half* __restrict__ dsth) {
    __shared__ float tile[32][33];
    int bh = blockIdx.z;
    int b = bh / H_, h = bh % H_;
    int c0 = blockIdx.y * 32;
    int w0 = blockIdx.x * 32;
    int tx = threadIdx.x, ty = threadIdx.y;
#pragma unroll
    for (int k = 0; k < 4; ++k) {
        int c = c0 + ty + k * 8;
        tile[ty + k * 8][tx] = src[(((size_t)b * C_ + c) * H_ + h) * W_ + w0 + tx];
    }
    __syncthreads();
#pragma unroll
    for (int k = 0; k < 4; ++k) {
        int w = w0 + ty + k * 8;
        dsth[(((size_t)b * W_ + w) * H_ + h) * C_ + c0 + tx] =
            __float2half(tile[tx][ty + k * 8]);
    }
}

// ===========================================================================
// fp16 mma GEMM. CTA 128x128, BK=64, 3-stage cp.async, ldmatrix.
// MODE 2: +bias32[n] ->half
// MODE 3: relu6 + cr32 gather -> fp32 BCHW scatter
// MODE 4: nhc->bchw scatter ->half (m is NHC token: srow = w*96+h)
// MODE 5: ->fp32
// MODE 6: fused N=1536 [K|V|KV]: seg0 -> C0 + half residual(extra=hv),
//         seg1 -> C1, seg2 -> C2
// ===========================================================================
#define BKH    64
#define SLDH   72
#define TILEH  (128 * SLDH)
#define STAGEB (2 * TILEH * 2)
#define GSMEM  (3 * STAGEB)

__device__ __forceinline__ void load_tile_h(
    const __half* __restrict__ A, const __half* __restrict__ Wt,
    int m0, int n0, int kt, uint32_t sa, uint32_t sb, int tid)
{
#pragma unroll
    for (int it = 0; it < 4; ++it) {
        int c = it * 256 + tid;
        int row = c >> 3;
        int seg = c & 7;
        CP_ASYNC16(sa + (row * SLDH + seg * 8) * 2,
                   A + (size_t)(m0 + row) * 512 + kt + seg * 8);
        CP_ASYNC16(sb + (row * SLDH + seg * 8) * 2,
                   Wt + (size_t)(n0 + row) * 512 + kt + seg * 8);
    }
}

template <int MODE>
__global__ __launch_bounds__(256, 2) void k_hgemm(
    const __half* __restrict__ A, const __half* __restrict__ Wt,
    void* __restrict__ Cv, const void* __restrict__ extra,
    void* __restrict__ C1, void* __restrict__ C2)
{
    extern __shared__ char smraw[];
    const uint32_t s0 = smem_u32(smraw);

    const int tid = threadIdx.x;
    const int m0 = blockIdx.y * 128;
    const int n0 = blockIdx.x * 128;
    const int wid = tid >> 5, lane = tid & 31;
    const int mw = (wid & 3) * 32;
    const int nw = (wid >> 2) * 64;
    const int g = lane >> 2, tig = lane & 3;

    uint32_t aoff[2], boff[4];
#pragma unroll
    for (int i = 0; i < 2; ++i)
        aoff[i] = ((mw + i * 16 + (lane & 15)) * SLDH + (lane >> 4) * 8) * 2;
#pragma unroll
    for (int jp = 0; jp < 4; ++jp)
        boff[jp] = (uint32_t)(TILEH * 2) +
                   ((nw + jp * 16 + ((lane & 7) | ((lane >> 4) << 3))) * SLDH +
                    ((lane >> 3) & 1) * 8) * 2;

    float d[2][8][4];
#pragma unroll
    for (int i = 0; i < 2; ++i)
#pragma unroll
        for (int j = 0; j < 8; ++j)
#pragma unroll
            for (int q = 0; q < 4; ++q) d[i][j][q] = 0.f;

    load_tile_h(A, Wt, m0, n0, 0,    s0,          s0 + TILEH * 2,          tid); CP_COMMIT();
    load_tile_h(A, Wt, m0, n0, BKH,  s0 + STAGEB, s0 + STAGEB + TILEH * 2, tid); CP_COMMIT();

#pragma unroll 1
    for (int t = 0; t < 8; ++t) {
        CP_WAIT1();
        __syncthreads();
        if (t + 2 < 8) {
            uint32_t sb = s0 + ((t + 2) % 3) * STAGEB;
            load_tile_h(A, Wt, m0, n0, (t + 2) * BKH, sb, sb + TILEH * 2, tid);
        }
        CP_COMMIT();
        const uint32_t st = s0 + (t % 3) * STAGEB;
#pragma unroll
        for (int kk = 0; kk < 4; ++kk) {
            const uint32_t kb = kk * 32;
            uint32_t af[2][4], bf[8][2];
#pragma unroll
            for (int i = 0; i < 2; ++i)
                LDSM_X4(af[i][0], af[i][1], af[i][2], af[i][3], st + aoff[i] + kb);
#pragma unroll
            for (int jp = 0; jp < 4; ++jp)
                LDSM_X4(bf[2 * jp][0], bf[2 * jp][1], bf[2 * jp + 1][0], bf[2 * jp + 1][1],
                        st + boff[jp] + kb);
#pragma unroll
            for (int i = 0; i < 2; ++i)
#pragma unroll
                for (int j = 0; j < 8; ++j)
                    mma_f16(d[i][j], af[i], bf[j]);
        }
    }

    // --- Epilogue ---
    // MODE 6 CTA-uniform segment select (tiles never straddle 512 boundary)
    __half* m6out = nullptr;
    bool m6res = false;
    if (MODE == 6) {
        int seg = n0 >> 9;
        m6out = (seg == 0) ? (__half*)Cv : (seg == 1) ? (__half*)C1 : (__half*)C2;
        m6res = (seg == 0);
    }

#pragma unroll
    for (int i = 0; i < 2; ++i) {
#pragma unroll
        for (int half_ = 0; half_ < 2; ++half_) {
            int m = m0 + mw + i * 16 + g + half_ * 8;
            if (MODE == 3 || MODE == 4) {
                int bb = m / HW_;
                int srow = m - bb * HW_;
                int p = srow / W_;
                int q = srow - p * W_;
                if (MODE == 3) {
                    const float* crp = (const float*)extra +
                                       (((size_t)(bb * W_ + q) * H_ + p) * 512);
                    float* outp = (float*)Cv + (size_t)bb * 512 * HW_ + srow;
#pragma unroll
                    for (int j = 0; j < 8; ++j) {
                        int nn = n0 + nw + j * 8 + 2 * tig;
                        float v0 = fminf(fmaxf(d[i][j][half_ * 2 + 0], 0.f), 6.f) + crp[nn];
                        float v1 = fminf(fmaxf(d[i][j][half_ * 2 + 1], 0.f), 6.f) + crp[nn + 1];
                        outp[(size_t)nn * HW_] = v0;
                        outp[(size_t)(nn + 1) * HW_] = v1;
                    }
                } else {
                    // m = b*9216 + w*96 + h  -> bchw offset h*96 + w = q*96 + p
                    __half* outp = (__half*)Cv + (size_t)bb * 512 * HW_ + q * W_ + p;
#pragma unroll
                    for (int j = 0; j < 8; ++j) {
                        int nn = n0 + nw + j * 8 + 2 * tig;
                        outp[(size_t)nn * HW_] = __float2half(d[i][j][half_ * 2 + 0]);
                        outp[(size_t)(nn + 1) * HW_] = __float2half(d[i][j][half_ * 2 + 1]);
                    }
                }
            } else if (MODE == 5) {
                float* cp = (float*)Cv + (size_t)m * 512;
#pragma unroll
                for (int j = 0; j < 8; ++j) {
                    int nn = n0 + nw + j * 8 + 2 * tig;
                    *(float2*)(cp + nn) =
                        make_float2(d[i][j][half_ * 2 + 0], d[i][j][half_ * 2 + 1]);
                }
            } else if (MODE == 6) {
                __half* cp = m6out + (size_t)m * 512;
                const __half* rp = (const __half*)extra + (size_t)m * 512;
#pragma unroll
                for (int j = 0; j < 8; ++j) {
                    int nn = n0 + nw + j * 8 + 2 * tig;
                    int col = nn & 511;
                    float v0 = d[i][j][half_ * 2 + 0];
                    float v1 = d[i][j][half_ * 2 + 1];
                    if (m6res) {
                        v0 += __half2float(rp[col]);
                        v1 += __half2float(rp[col + 1]);
                    }
                    *(uint32_t*)(cp + col) = pack2h(v0, v1);
                }
            } else {  // MODE 2: bias
                __half* cp = (__half*)Cv + (size_t)m * 512;
                const float* ep = (const float*)extra;
#pragma unroll
                for (int j = 0; j < 8; ++j) {
                    int nn = n0 + nw + j * 8 + 2 * tig;
                    float v0 = d[i][j][half_ * 2 + 0] + ep[nn];
                    float v1 = d[i][j][half_ * 2 + 1] + ep[nn + 1];
                    *(uint32_t*)(cp + nn) = pack2h(v0, v1);
                }
            }
        }
    }
}

// ===========================================================================
// Flash-style fp16 attention (unchanged, proven in R8)
// ===========================================================================
#define AQLD 72
#define AVLD 104
#define ATTN_SMEM ((2 * 96 * AQLD + 64 * AVLD) * 2)

__global__ __launch_bounds__(192, 3) void k_attn_h(
    const __half* __restrict__ Q, const __half* __restrict__ Kt,
    const __half* __restrict__ Vt, __half* __restrict__ O)
{
    extern __shared__ char smraw[];
    const uint32_t sQ = smem_u32(smraw);
    const uint32_t sK = sQ + 96 * AQLD * 2;
    const uint32_t sV = sK + 96 * AQLD * 2;
    __half* sVh = (__half*)(smraw + 2 * 96 * AQLD * 2);

    const int tid = threadIdx.x;
    const int n = blockIdx.x >> 3;
    const int hd = blockIdx.x & 7;
    const size_t base = (size_t)n * 96 * 512 + hd * DH;

    for (int i = tid; i < 96 * 8; i += 192) {
        int r = i >> 3, seg = i & 7;
        CP_ASYNC16(sQ + (r * AQLD + seg * 8) * 2, Q  + base + (size_t)r * 512 + seg * 8);
        CP_ASYNC16(sK + (r * AQLD + seg * 8) * 2, Kt + base + (size_t)r * 512 + seg * 8);
    }
    CP_COMMIT();
    for (int i = tid; i < 96 * 8; i += 192) {
        int key = i >> 3, d8 = (i & 7) * 8;
        uint4 v = *(const uint4*)(Vt + base + (size_t)key * 512 + d8);
        __half2 hh[4];
        memcpy(hh, &v, 16);
#pragma unroll
        for (int q = 0; q < 4; ++q) {
            sVh[(d8 + 2 * q) * AVLD + key]     = __low2half(hh[q]);
            sVh[(d8 + 2 * q + 1) * AVLD + key] = __high2half(hh[q]);
        }
    }
    CP_WAIT0();
    __syncthreads();

    const int wid = tid / 32, lane = tid % 32;
    const int g = lane >> 2, tig = lane & 3;
    const int m0 = wid * 16;

    const uint32_t aAddr = sQ + ((m0 + (lane & 15)) * AQLD + (lane >> 4) * 8) * 2;
    const uint32_t bRow = (lane & 7) | ((lane >> 4) << 3);
    const uint32_t bCol = ((lane >> 3) & 1) * 8;

    float dS[12][4];
#pragma unroll
    for (int j = 0; j < 12; ++j)
#pragma unroll
        for (int q = 0; q < 4; ++q) dS[j][q] = 0.f;

#pragma unroll
    for (int kk = 0; kk < 4; ++kk) {
        uint32_t af[4];
        LDSM_X4(af[0], af[1], af[2], af[3], aAddr + kk * 32);
#pragma unroll
        for (int jp = 0; jp < 6; ++jp) {
            uint32_t b0, b1, b2, b3;
            LDSM_X4(b0, b1, b2, b3,
                    sK + ((jp * 16 + bRow) * AQLD + bCol) * 2 + kk * 32);
            uint32_t bA[2] = {b0, b1}, bB[2] = {b2, b3};
            mma_f16(dS[2 * jp], af, bA);
            mma_f16(dS[2 * jp + 1], af, bB);
        }
    }

    float mx0 = -1e30f, mx1 = -1e30f;
#pragma unroll
    for (int j = 0; j < 12; ++j) {
        dS[j][0] *= 0.125f; dS[j][1] *= 0.125f;
        dS[j][2] *= 0.125f; dS[j][3] *= 0.125f;
        mx0 = fmaxf(mx0, fmaxf(dS[j][0], dS[j][1]));
        mx1 = fmaxf(mx1, fmaxf(dS[j][2], dS[j][3]));
    }
    mx0 = fmaxf(mx0, __shfl_xor_sync(0xffffffffu, mx0, 1));
    mx0 = fmaxf(mx0, __shfl_xor_sync(0xffffffffu, mx0, 2));
    mx1 = fmaxf(mx1, __shfl_xor_sync(0xffffffffu, mx1, 1));
    mx1 = fmaxf(mx1, __shfl_xor_sync(0xffffffffu, mx1, 2));
    float s0 = 0.f, s1 = 0.f;
#pragma unroll
    for (int j = 0; j < 12; ++j) {
        dS[j][0] = __expf(dS[j][0] - mx0); dS[j][1] = __expf(dS[j][1] - mx0);
        dS[j][2] = __expf(dS[j][2] - mx1); dS[j][3] = __expf(dS[j][3] - mx1);
        s0 += dS[j][0] + dS[j][1];
        s1 += dS[j][2] + dS[j][3];
    }
    s0 += __shfl_xor_sync(0xffffffffu, s0, 1);
    s0 += __shfl_xor_sync(0xffffffffu, s0, 2);
    s1 += __shfl_xor_sync(0xffffffffu, s1, 1);
    s1 += __shfl_xor_sync(0xffffffffu, s1, 2);
    const float i0 = 1.f / s0, i1 = 1.f / s1;

    uint32_t aP[6][4];
#pragma unroll
    for (int kk = 0; kk < 6; ++kk) {
        aP[kk][0] = pack2h(dS[2 * kk][0] * i0, dS[2 * kk][1] * i0);
        aP[kk][1] = pack2h(dS[2 * kk][2] * i1, dS[2 * kk][3] * i1);
        aP[kk][2] = pack2h(dS[2 * kk + 1][0] * i0, dS[2 * kk + 1][1] * i0);
        aP[kk][3] = pack2h(dS[2 * kk + 1][2] * i1, dS[2 * kk + 1][3] * i1);
    }

    float dO[8][4];
#pragma unroll
    for (int j = 0; j < 8; ++j)
#pragma unroll
        for (int q = 0; q < 4; ++q) dO[j][q] = 0.f;

#pragma unroll
    for (int kk = 0; kk < 6; ++kk) {
        uint32_t bf[8][2];
#pragma unroll
        for (int jp = 0; jp < 4; ++jp)
            LDSM_X4(bf[2 * jp][0], bf[2 * jp][1], bf[2 * jp + 1][0], bf[2 * jp + 1][1],
                    sV + ((jp * 16 + bRow) * AVLD + bCol) * 2 + kk * 32);
#pragma unroll
        for (int j = 0; j < 8; ++j)
            mma_f16(dO[j], aP[kk], bf[j]);
    }

#pragma unroll
    for (int j = 0; j < 8; ++j) {
        int col = j * 8 + 2 * tig;
        *(uint32_t*)(O + base + (size_t)(m0 + g) * 512 + col) =
            pack2h(dO[j][0], dO[j][1]);
        *(uint32_t*)(O + base + (size_t)(m0 + g + 8) * 512 + col) =
            pack2h(dO[j][2], dO[j][3]);
    }
}

// ===========================================================================
// Depthwise 3x3 + BN -> token-major half, COALESCED writes.
// Block = 16 channels x 256 tokens. Grid (36, 32, 8).
// ===========================================================================
__global__ __launch_bounds__(256) void k_dwconv2(
    const float* __restrict__ x, const float* __restrict__ wgt,
    const float* __restrict__ bg, const float* __restrict__ bb_,
    const float* __restrict__ bm, const float* __restrict__ bv,
    __half* __restrict__ y)
{
    __shared__ float taps[16][9];
    __shared__ float psc[16], pmm[16], pbb[16];
    __shared__ uint32_t sOut[256 * 9];      // stride 9: conflict-free

    const int tid = threadIdx.x;
    const int c0 = blockIdx.y * 16, b = blockIdx.z, s0 = blockIdx.x * 256;

    if (tid < 16 * 9) taps[tid / 9][tid % 9] = wgt[(c0 + tid / 9) * 9 + tid % 9];
    else if (tid < 160) {
        int ch = tid - 144;
        psc[ch] = bg[c0 + ch] * rsqrtf(bv[c0 + ch] + 1e-5f);
        pmm[ch] = bm[c0 + ch];
        pbb[ch] = bb_[c0 + ch];
    }
    __syncthreads();

    const int s = s0 + tid;
    const int h = s / W_, w = s - (s / W_) * W_;
    const bool hm = h > 0, hp = h < H_ - 1, wm = w > 0, wp = w < W_ - 1;

    float acc[16];
#pragma unroll
    for (int ch = 0; ch < 16; ++ch) {
        const float* xc = x + ((size_t)b * C_ + c0 + ch) * HW_ + s;
        const float* tp = taps[ch];
        float a = xc[0] * tp[4];
        if (wm) a = fmaf(xc[-1], tp[3], a);
        if (wp) a = fmaf(xc[1],  tp[5], a);
        if (hm) {
            a = fmaf(xc[-W_], tp[1], a);
            if (wm) a = fmaf(xc[-W_ - 1], tp[0], a);
            if (wp) a = fmaf(xc[-W_ + 1], tp[2], a);
        }
        if (hp) {
            a = fmaf(xc[W_], tp[7], a);
            if (wm) a = fmaf(xc[W_ - 1], tp[6], a);
            if (wp) a = fmaf(xc[W_ + 1], tp[8], a);
        }
        acc[ch] = (a - pmm[ch]) * psc[ch] + pbb[ch];
    }
#pragma unroll
    for (int q = 0; q < 8; ++q)
        sOut[tid * 9 + q] = pack2h(acc[2 * q], acc[2 * q + 1]);
    __syncthreads();

    // coalesced write: 8 uint32 (16 halves) per token, consecutive lanes
    uint32_t* y32 = (uint32_t*)y;
    const size_t rowbase = ((size_t)b * HW_ + s0) * 256 + (c0 >> 1);
#pragma unroll
    for (int it = 0; it < 8; ++it) {
        int i = it * 256 + tid;
        int token = i >> 3, q = i & 7;
        y32[rowbase + (size_t)token * 256 + q] = sOut[token * 9 + q];
    }
}

// ===========================================================================
// Launch
// ===========================================================================
extern "C" void kernel_launch(void* const* d_in, const int* in_sizes, int n_in,
                              void* d_out, int out_size)
{
    const float* x      = (const float*)d_in[0];
    const float* msa_Wk = (const float*)d_in[1];
    const float* msa_Wv = (const float*)d_in[2];
    const float* msa_Wo = (const float*)d_in[3];
    const float* cr_Wq  = (const float*)d_in[4];
    const float* cr_bq  = (const float*)d_in[5];
    const float* cr_Wv  = (const float*)d_in[6];
    const float* cr_Wo  = (const float*)d_in[7];
    const float* dw_w   = (const float*)d_in[8];
    const float* bn_g   = (const float*)d_in[9];
    const float* bn_b   = (const float*)d_in[10];
    const float* bn_m   = (const float*)d_in[11];
    const float* bn_v   = (const float*)d_in[12];
    const float* pw_w   = (const float*)d_in[13];
    float* out = (float*)d_out;

    float* f32;  __half *hv, *hA, *hB, *hC, *hD, *hE, *wh;
    cudaGetSymbolAddress((void**)&f32, g_f32);
    cudaGetSymbolAddress((void**)&hv, g_hv);
    cudaGetSymbolAddress((void**)&hA, g_hA);
    cudaGetSymbolAddress((void**)&hB, g_hB);
    cudaGetSymbolAddress((void**)&hC, g_hC);
    cudaGetSymbolAddress((void**)&hD, g_hD);
    cudaGetSymbolAddress((void**)&hE, g_hE);
    cudaGetSymbolAddress((void**)&wh, g_wh);

    cudaFuncSetAttribute(k_hgemm<2>, cudaFuncAttributeMaxDynamicSharedMemorySize, GSMEM);
    cudaFuncSetAttribute(k_hgemm<3>, cudaFuncAttributeMaxDynamicSharedMemorySize, GSMEM);
    cudaFuncSetAttribute(k_hgemm<4>, cudaFuncAttributeMaxDynamicSharedMemorySize, GSMEM);
    cudaFuncSetAttribute(k_hgemm<5>, cudaFuncAttributeMaxDynamicSharedMemorySize, GSMEM);
    cudaFuncSetAttribute(k_hgemm<6>, cudaFuncAttributeMaxDynamicSharedMemorySize, GSMEM);

    // 0. all weights -> half, one launch
    k_w2h_all<<<(7 * WN + 255) / 256, 256>>>(msa_Wk, msa_Wv, cr_Wv, msa_Wo,
                                             cr_Wq, cr_Wo, pw_w, wh);

    dim3 tgrid(3, 16, B_ * H_), tblk(32, 8);
    dim3 ggrid(4, NTOK / 128), gblk(256);
    dim3 g6grid(12, NTOK / 128);
    dim3 dgrid(HW_ / 256, C_ / 16, B_);

    // 1. vqk = permute(x) (half)
    k_bchw_to_nhc<<<tgrid, tblk>>>(x, hv);
    // 2. fused [K|V|KV] = vqk @ [Wk|Wv|crWv]^T (K += vqk residual)
    k_hgemm<6><<<g6grid, gblk, GSMEM>>>(hv, wh, hA, hv, hB, hC);
    // 3. attn(vqk, K, V) -> hD
    k_attn_h<<<B_ * W_ * NHEAD, 192, ATTN_SMEM>>>(hv, hA, hB, hD);
    // 4. O = attn@Wo^T, fused nhc->bchw scatter -> hE (= q_view)
    k_hgemm<4><<<ggrid, gblk, GSMEM>>>(hD, wh + 3 * WN, hE, nullptr, nullptr, nullptr);
    // 5. Q2 = q_view@crWq^T + bq -> hA
    k_hgemm<2><<<ggrid, gblk, GSMEM>>>(hE, wh + 4 * WN, hA, cr_bq, nullptr, nullptr);
    // 6. attn(Q2, KV, KV) -> hB
    k_attn_h<<<B_ * W_ * NHEAD, 192, ATTN_SMEM>>>(hA, hC, hC, hB);
    // 7. CR = crattn@crWo^T -> f32
    k_hgemm<5><<<ggrid, gblk, GSMEM>>>(hB, wh + 5 * WN, f32, nullptr, nullptr, nullptr);
    // 8. depthwise+BN -> hD (half, token-major, coalesced)
    k_dwconv2<<<dgrid, 256>>>(x, dw_w, bn_g, bn_b, bn_m, bn_v, hD);
    // 9. out = clip(hD@pw^T,0,6) + permute(CR) -> BCHW fp32
    k_hgemm<3><<<ggrid, gblk, GSMEM>>>(hD, wh + 6 * WN, out, f32, nullptr, nullptr);
}

// round 10
// speedup vs baseline: 5.8910x; 1.1967x over previous
#include <cuda_runtime.h>
#include <cuda_fp16.h>
#include <cstdint>
#include <string.h>
#include <math.h>

#define B_    8
#define C_    512
#define H_    96
#define W_    96
#define HW_   9216
#define NTOK  73728
#define IMGN  37748736
#define NHEAD 8
#define DH    64
#define WN    262144          // C_*C_ = 2^18

// Scratch buffers (all half now; CR kept in half)
__device__ __half g_hv[IMGN];
__device__ __half g_hA[IMGN];
__device__ __half g_hB[IMGN];
__device__ __half g_hC[IMGN];
__device__ __half g_hD[IMGN];
__device__ __half g_hE[IMGN];
__device__ __half g_wh[7 * WN];

// ===========================================================================
// PTX helpers
// ===========================================================================
__device__ __forceinline__ uint32_t smem_u32(const void* p) {
    uint32_t a;
    asm("{ .reg .u64 t; cvta.to.shared.u64 t, %1; cvt.u32.u64 %0, t; }"
        : "=r"(a) : "l"(p));
    return a;
}
#define CP_ASYNC16(dst, src) \
    asm volatile("cp.async.cg.shared.global [%0], [%1], 16;" :: "r"(dst), "l"(src))
#define CP_COMMIT() asm volatile("cp.async.commit_group;" ::: "memory")
#define CP_WAIT0()  asm volatile("cp.async.wait_group 0;" ::: "memory")
#define CP_WAIT1()  asm volatile("cp.async.wait_group 1;" ::: "memory")

#define LDSM_X4(r0, r1, r2, r3, addr) \
    asm volatile("ldmatrix.sync.aligned.m8n8.x4.shared.b16 {%0,%1,%2,%3}, [%4];" \
        : "=r"(r0), "=r"(r1), "=r"(r2), "=r"(r3) : "r"(addr))

__device__ __forceinline__ void mma_f16(float* d, const uint32_t* a, const uint32_t* b) {
    asm volatile(
        "mma.sync.aligned.m16n8k16.row.col.f32.f16.f16.f32 "
        "{%0,%1,%2,%3}, {%4,%5,%6,%7}, {%8,%9}, {%0,%1,%2,%3};"
        : "+f"(d[0]), "+f"(d[1]), "+f"(d[2]), "+f"(d[3])
        : "r"(a[0]), "r"(a[1]), "r"(a[2]), "r"(a[3]), "r"(b[0]), "r"(b[1]));
}

__device__ __forceinline__ uint32_t pack2h(float x, float y) {
    __half2 h = __floats2half2_rn(x, y);
    uint32_t u;
    memcpy(&u, &h, 4);
    return u;
}

// ===========================================================================
// All weights fp32 -> fp16 in ONE launch.
// Slots: 0=Wk 1=Wv 2=crWv (fused GEMM B) | 3=Wo 4=crWq 5=crWo 6=pw
// ===========================================================================
__global__ void k_w2h_all(const float* __restrict__ wk, const float* __restrict__ wv,
                          const float* __restrict__ cwv, const float* __restrict__ wo,
                          const float* __restrict__ cwq, const float* __restrict__ cwo,
                          const float* __restrict__ pw, __half* __restrict__ o) {
    int i = blockIdx.x * 256 + threadIdx.x;
    if (i >= 7 * WN) return;
    int slot = i >> 18, off = i & (WN - 1);
    const float* src;
    switch (slot) {
        case 0: src = wk;  break;
        case 1: src = wv;  break;
        case 2: src = cwv; break;
        case 3: src = wo;  break;
        case 4: src = cwq; break;
        case 5: src = cwo; break;
        default: src = pw; break;
    }
    o[i] = __float2half(src[off]);
}

// ===========================================================================
// Transpose bchw(f32) -> nhc(half)
// ===========================================================================
__global__ void k_bchw_to_nhc(const float* __restrict__ src, __half* __restrict__ dsth) {
    __shared__ float tile[32][33];
    int bh = blockIdx.z;
    int b = bh / H_, h = bh % H_;
    int c0 = blockIdx.y * 32;
    int w0 = blockIdx.x * 32;
    int tx = threadIdx.x, ty = threadIdx.y;
#pragma unroll
    for (int k = 0; k < 4; ++k) {
        int c = c0 + ty + k * 8;
        tile[ty + k * 8][tx] = src[(((size_t)b * C_ + c) * H_ + h) * W_ + w0 + tx];
    }
    __syncthreads();
#pragma unroll
    for (int k = 0; k < 4; ++k) {
        int w = w0 + ty + k * 8;
        dsth[(((size_t)b * W_ + w) * H_ + h) * C_ + c0 + tx] =
            __float2half(tile[tx][ty + k * 8]);
    }
}

// ===========================================================================
// Transpose nhc(half) -> bchw-flat(half)  (the q_view reshape)
// Coalesced 64B on both sides via smem tile.
// ===========================================================================
__global__ void k_nhc_to_bchw_h(const __half* __restrict__ src, __half* __restrict__ dst) {
    __shared__ __half tile[32][34];
    int bh = blockIdx.z;
    int b = bh / H_, h = bh % H_;
    int c0 = blockIdx.y * 32;
    int w0 = blockIdx.x * 32;
    int tx = threadIdx.x, ty = threadIdx.y;
#pragma unroll
    for (int k = 0; k < 4; ++k) {
        int w = w0 + ty + k * 8;
        tile[ty + k * 8][tx] = src[(((size_t)b * W_ + w) * H_ + h) * C_ + c0 + tx];
    }
    __syncthreads();
#pragma unroll
    for (int k = 0; k < 4; ++k) {
        int c = c0 + ty + k * 8;
        dst[(((size_t)b * C_ + c) * H_ + h) * W_ + w0 + tx] = tile[tx][ty + k * 8];
    }
}

// ===========================================================================
// fp16 mma GEMM. CTA 128x128, BK=64, 3-stage cp.async, ldmatrix.
// MODE 0: plain ->half
// MODE 2: +bias32[n] ->half
// MODE 3: relu6 + CR(half, same token order) -> fp32 BCHW scatter
// MODE 6: fused N=1536 [K|V|KV]: seg0 -> Cv + half residual(extra), seg1->C1, seg2->C2
// ===========================================================================
#define BKH    64
#define SLDH   72
#define TILEH  (128 * SLDH)
#define STAGEB (2 * TILEH * 2)
#define GSMEM  (3 * STAGEB)

__device__ __forceinline__ void load_tile_h(
    const __half* __restrict__ A, const __half* __restrict__ Wt,
    int m0, int n0, int kt, uint32_t sa, uint32_t sb, int tid)
{
#pragma unroll
    for (int it = 0; it < 4; ++it) {
        int c = it * 256 + tid;
        int row = c >> 3;
        int seg = c & 7;
        CP_ASYNC16(sa + (row * SLDH + seg * 8) * 2,
                   A + (size_t)(m0 + row) * 512 + kt + seg * 8);
        CP_ASYNC16(sb + (row * SLDH + seg * 8) * 2,
                   Wt + (size_t)(n0 + row) * 512 + kt + seg * 8);
    }
}

template <int MODE>
__global__ __launch_bounds__(256, 2) void k_hgemm(
    const __half* __restrict__ A, const __half* __restrict__ Wt,
    void* __restrict__ Cv, const void* __restrict__ extra,
    void* __restrict__ C1, void* __restrict__ C2)
{
    extern __shared__ char smraw[];
    const uint32_t s0 = smem_u32(smraw);

    const int tid = threadIdx.x;
    const int m0 = blockIdx.y * 128;
    const int n0 = blockIdx.x * 128;
    const int wid = tid >> 5, lane = tid & 31;
    const int mw = (wid & 3) * 32;
    const int nw = (wid >> 2) * 64;
    const int g = lane >> 2, tig = lane & 3;

    uint32_t aoff[2], boff[4];
#pragma unroll
    for (int i = 0; i < 2; ++i)
        aoff[i] = ((mw + i * 16 + (lane & 15)) * SLDH + (lane >> 4) * 8) * 2;
#pragma unroll
    for (int jp = 0; jp < 4; ++jp)
        boff[jp] = (uint32_t)(TILEH * 2) +
                   ((nw + jp * 16 + ((lane & 7) | ((lane >> 4) << 3))) * SLDH +
                    ((lane >> 3) & 1) * 8) * 2;

    float d[2][8][4];
#pragma unroll
    for (int i = 0; i < 2; ++i)
#pragma unroll
        for (int j = 0; j < 8; ++j)
#pragma unroll
            for (int q = 0; q < 4; ++q) d[i][j][q] = 0.f;

    load_tile_h(A, Wt, m0, n0, 0,    s0,          s0 + TILEH * 2,          tid); CP_COMMIT();
    load_tile_h(A, Wt, m0, n0, BKH,  s0 + STAGEB, s0 + STAGEB + TILEH * 2, tid); CP_COMMIT();

#pragma unroll 1
    for (int t = 0; t < 8; ++t) {
        CP_WAIT1();
        __syncthreads();
        if (t + 2 < 8) {
            uint32_t sb = s0 + ((t + 2) % 3) * STAGEB;
            load_tile_h(A, Wt, m0, n0, (t + 2) * BKH, sb, sb + TILEH * 2, tid);
        }
        CP_COMMIT();
        const uint32_t st = s0 + (t % 3) * STAGEB;
#pragma unroll
        for (int kk = 0; kk < 4; ++kk) {
            const uint32_t kb = kk * 32;
            uint32_t af[2][4], bf[8][2];
#pragma unroll
            for (int i = 0; i < 2; ++i)
                LDSM_X4(af[i][0], af[i][1], af[i][2], af[i][3], st + aoff[i] + kb);
#pragma unroll
            for (int jp = 0; jp < 4; ++jp)
                LDSM_X4(bf[2 * jp][0], bf[2 * jp][1], bf[2 * jp + 1][0], bf[2 * jp + 1][1],
                        st + boff[jp] + kb);
#pragma unroll
            for (int i = 0; i < 2; ++i)
#pragma unroll
                for (int j = 0; j < 8; ++j)
                    mma_f16(d[i][j], af[i], bf[j]);
        }
    }

    // --- Epilogue ---
    __half* m6out = nullptr;
    bool m6res = false;
    if (MODE == 6) {
        int seg = n0 >> 9;
        m6out = (seg == 0) ? (__half*)Cv : (seg == 1) ? (__half*)C1 : (__half*)C2;
        m6res = (seg == 0);
    }

#pragma unroll
    for (int i = 0; i < 2; ++i) {
#pragma unroll
        for (int half_ = 0; half_ < 2; ++half_) {
            int m = m0 + mw + i * 16 + g + half_ * 8;
            if (MODE == 3) {
                int bb = m / HW_;
                int srow = m - bb * HW_;
                // CR (half) shares this kernel's token order -> coalesced
                const __half* crp = (const __half*)extra + (size_t)m * 512;
                float* outp = (float*)Cv + (size_t)bb * 512 * HW_ + srow;
#pragma unroll
                for (int j = 0; j < 8; ++j) {
                    int nn = n0 + nw + j * 8 + 2 * tig;
                    uint32_t cr2 = *(const uint32_t*)(crp + nn);
                    __half2 ch; memcpy(&ch, &cr2, 4);
                    float v0 = fminf(fmaxf(d[i][j][half_ * 2 + 0], 0.f), 6.f) + __low2float(ch);
                    float v1 = fminf(fmaxf(d[i][j][half_ * 2 + 1], 0.f), 6.f) + __high2float(ch);
                    outp[(size_t)nn * HW_] = v0;
                    outp[(size_t)(nn + 1) * HW_] = v1;
                }
            } else if (MODE == 6) {
                __half* cp = m6out + (size_t)m * 512;
                const __half* rp = (const __half*)extra + (size_t)m * 512;
#pragma unroll
                for (int j = 0; j < 8; ++j) {
                    int nn = n0 + nw + j * 8 + 2 * tig;
                    int col = nn & 511;
                    float v0 = d[i][j][half_ * 2 + 0];
                    float v1 = d[i][j][half_ * 2 + 1];
                    if (m6res) {
                        uint32_t r2 = *(const uint32_t*)(rp + col);
                        __half2 rh; memcpy(&rh, &r2, 4);
                        v0 += __low2float(rh);
                        v1 += __high2float(rh);
                    }
                    *(uint32_t*)(cp + col) = pack2h(v0, v1);
                }
            } else {  // MODE 0 / 2
                __half* cp = (__half*)Cv + (size_t)m * 512;
                const float* ep = (const float*)extra;
#pragma unroll
                for (int j = 0; j < 8; ++j) {
                    int nn = n0 + nw + j * 8 + 2 * tig;
                    float v0 = d[i][j][half_ * 2 + 0];
                    float v1 = d[i][j][half_ * 2 + 1];
                    if (MODE == 2) { v0 += ep[nn]; v1 += ep[nn + 1]; }
                    *(uint32_t*)(cp + nn) = pack2h(v0, v1);
                }
            }
        }
    }
}

// ===========================================================================
// Flash-style fp16 attention. PERM=true permutes OUTPUT tokens bwh->bhw
// (free: per-row writes stay contiguous). 4 CTAs/SM.
// ===========================================================================
#define AQLD 72
#define AVLD 104
#define ATTN_SMEM ((2 * 96 * AQLD + 64 * AVLD) * 2)

template <bool PERM>
__global__ __launch_bounds__(192, 4) void k_attn_h(
    const __half* __restrict__ Q, const __half* __restrict__ Kt,
    const __half* __restrict__ Vt, __half* __restrict__ O)
{
    extern __shared__ char smraw[];
    const uint32_t sQ = smem_u32(smraw);
    const uint32_t sK = sQ + 96 * AQLD * 2;
    const uint32_t sV = sK + 96 * AQLD * 2;
    __half* sVh = (__half*)(smraw + 2 * 96 * AQLD * 2);

    const int tid = threadIdx.x;
    const int n = blockIdx.x >> 3;
    const int hd = blockIdx.x & 7;
    const size_t base = (size_t)n * 96 * 512 + hd * DH;

    size_t obase, orow;
    if (PERM) {
        int b = n / 96, w = n - (n / 96) * 96;
        obase = (size_t)b * 9216 * 512 + (size_t)w * 512 + hd * DH;
        orow = 96 * 512;
    } else {
        obase = base;
        orow = 512;
    }

    for (int i = tid; i < 96 * 8; i += 192) {
        int r = i >> 3, seg = i & 7;
        CP_ASYNC16(sQ + (r * AQLD + seg * 8) * 2, Q  + base + (size_t)r * 512 + seg * 8);
        CP_ASYNC16(sK + (r * AQLD + seg * 8) * 2, Kt + base + (size_t)r * 512 + seg * 8);
    }
    CP_COMMIT();
    for (int i = tid; i < 96 * 8; i += 192) {
        int key = i >> 3, d8 = (i & 7) * 8;
        uint4 v = *(const uint4*)(Vt + base + (size_t)key * 512 + d8);
        __half2 hh[4];
        memcpy(hh, &v, 16);
#pragma unroll
        for (int q = 0; q < 4; ++q) {
            sVh[(d8 + 2 * q) * AVLD + key]     = __low2half(hh[q]);
            sVh[(d8 + 2 * q + 1) * AVLD + key] = __high2half(hh[q]);
        }
    }
    CP_WAIT0();
    __syncthreads();

    const int wid = tid / 32, lane = tid % 32;
    const int g = lane >> 2, tig = lane & 3;
    const int m0 = wid * 16;

    const uint32_t aAddr = sQ + ((m0 + (lane & 15)) * AQLD + (lane >> 4) * 8) * 2;
    const uint32_t bRow = (lane & 7) | ((lane >> 4) << 3);
    const uint32_t bCol = ((lane >> 3) & 1) * 8;

    float dS[12][4];
#pragma unroll
    for (int j = 0; j < 12; ++j)
#pragma unroll
        for (int q = 0; q < 4; ++q) dS[j][q] = 0.f;

#pragma unroll
    for (int kk = 0; kk < 4; ++kk) {
        uint32_t af[4];
        LDSM_X4(af[0], af[1], af[2], af[3], aAddr + kk * 32);
#pragma unroll
        for (int jp = 0; jp < 6; ++jp) {
            uint32_t b0, b1, b2, b3;
            LDSM_X4(b0, b1, b2, b3,
                    sK + ((jp * 16 + bRow) * AQLD + bCol) * 2 + kk * 32);
            uint32_t bA[2] = {b0, b1}, bB[2] = {b2, b3};
            mma_f16(dS[2 * jp], af, bA);
            mma_f16(dS[2 * jp + 1], af, bB);
        }
    }

    float mx0 = -1e30f, mx1 = -1e30f;
#pragma unroll
    for (int j = 0; j < 12; ++j) {
        dS[j][0] *= 0.125f; dS[j][1] *= 0.125f;
        dS[j][2] *= 0.125f; dS[j][3] *= 0.125f;
        mx0 = fmaxf(mx0, fmaxf(dS[j][0], dS[j][1]));
        mx1 = fmaxf(mx1, fmaxf(dS[j][2], dS[j][3]));
    }
    mx0 = fmaxf(mx0, __shfl_xor_sync(0xffffffffu, mx0, 1));
    mx0 = fmaxf(mx0, __shfl_xor_sync(0xffffffffu, mx0, 2));
    mx1 = fmaxf(mx1, __shfl_xor_sync(0xffffffffu, mx1, 1));
    mx1 = fmaxf(mx1, __shfl_xor_sync(0xffffffffu, mx1, 2));
    float s0 = 0.f, s1 = 0.f;
#pragma unroll
    for (int j = 0; j < 12; ++j) {
        dS[j][0] = __expf(dS[j][0] - mx0); dS[j][1] = __expf(dS[j][1] - mx0);
        dS[j][2] = __expf(dS[j][2] - mx1); dS[j][3] = __expf(dS[j][3] - mx1);
        s0 += dS[j][0] + dS[j][1];
        s1 += dS[j][2] + dS[j][3];
    }
    s0 += __shfl_xor_sync(0xffffffffu, s0, 1);
    s0 += __shfl_xor_sync(0xffffffffu, s0, 2);
    s1 += __shfl_xor_sync(0xffffffffu, s1, 1);
    s1 += __shfl_xor_sync(0xffffffffu, s1, 2);
    const float i0 = 1.f / s0, i1 = 1.f / s1;

    uint32_t aP[6][4];
#pragma unroll
    for (int kk = 0; kk < 6; ++kk) {
        aP[kk][0] = pack2h(dS[2 * kk][0] * i0, dS[2 * kk][1] * i0);
        aP[kk][1] = pack2h(dS[2 * kk][2] * i1, dS[2 * kk][3] * i1);
        aP[kk][2] = pack2h(dS[2 * kk + 1][0] * i0, dS[2 * kk + 1][1] * i0);
        aP[kk][3] = pack2h(dS[2 * kk + 1][2] * i1, dS[2 * kk + 1][3] * i1);
    }

    float dO[8][4];
#pragma unroll
    for (int j = 0; j < 8; ++j)
#pragma unroll
        for (int q = 0; q < 4; ++q) dO[j][q] = 0.f;

#pragma unroll
    for (int kk = 0; kk < 6; ++kk) {
        uint32_t bf[8][2];
#pragma unroll
        for (int jp = 0; jp < 4; ++jp)
            LDSM_X4(bf[2 * jp][0], bf[2 * jp][1], bf[2 * jp + 1][0], bf[2 * jp + 1][1],
                    sV + ((jp * 16 + bRow) * AVLD + bCol) * 2 + kk * 32);
#pragma unroll
        for (int j = 0; j < 8; ++j)
            mma_f16(dO[j], aP[kk], bf[j]);
    }

#pragma unroll
    for (int j = 0; j < 8; ++j) {
        int col = j * 8 + 2 * tig;
        *(uint32_t*)(O + obase + (size_t)(m0 + g) * orow + col) =
            pack2h(dO[j][0], dO[j][1]);
        *(uint32_t*)(O + obase + (size_t)(m0 + g + 8) * orow + col) =
            pack2h(dO[j][2], dO[j][3]);
    }
}

// ===========================================================================
// Depthwise 3x3 + BN -> token-major half, coalesced writes (proven R9)
// ===========================================================================
__global__ __launch_bounds__(256) void k_dwconv2(
    const float* __restrict__ x, const float* __restrict__ wgt,
    const float* __restrict__ bg, const float* __restrict__ bb_,
    const float* __restrict__ bm, const float* __restrict__ bv,
    __half* __restrict__ y)
{
    __shared__ float taps[16][9];
    __shared__ float psc[16], pmm[16], pbb[16];
    __shared__ uint32_t sOut[256 * 9];

    const int tid = threadIdx.x;
    const int c0 = blockIdx.y * 16, b = blockIdx.z, s0 = blockIdx.x * 256;

    if (tid < 16 * 9) taps[tid / 9][tid % 9] = wgt[(c0 + tid / 9) * 9 + tid % 9];
    else if (tid < 160) {
        int ch = tid - 144;
        psc[ch] = bg[c0 + ch] * rsqrtf(bv[c0 + ch] + 1e-5f);
        pmm[ch] = bm[c0 + ch];
        pbb[ch] = bb_[c0 + ch];
    }
    __syncthreads();

    const int s = s0 + tid;
    const int h = s / W_, w = s - (s / W_) * W_;
    const bool hm = h > 0, hp = h < H_ - 1, wm = w > 0, wp = w < W_ - 1;

    float acc[16];
#pragma unroll
    for (int ch = 0; ch < 16; ++ch) {
        const float* xc = x + ((size_t)b * C_ + c0 + ch) * HW_ + s;
        const float* tp = taps[ch];
        float a = xc[0] * tp[4];
        if (wm) a = fmaf(xc[-1], tp[3], a);
        if (wp) a = fmaf(xc[1],  tp[5], a);
        if (hm) {
            a = fmaf(xc[-W_], tp[1], a);
            if (wm) a = fmaf(xc[-W_ - 1], tp[0], a);
            if (wp) a = fmaf(xc[-W_ + 1], tp[2], a);
        }
        if (hp) {
            a = fmaf(xc[W_], tp[7], a);
            if (wm) a = fmaf(xc[W_ - 1], tp[6], a);
            if (wp) a = fmaf(xc[W_ + 1], tp[8], a);
        }
        acc[ch] = (a - pmm[ch]) * psc[ch] + pbb[ch];
    }
#pragma unroll
    for (int q = 0; q < 8; ++q)
        sOut[tid * 9 + q] = pack2h(acc[2 * q], acc[2 * q + 1]);
    __syncthreads();

    uint32_t* y32 = (uint32_t*)y;
    const size_t rowbase = ((size_t)b * HW_ + s0) * 256 + (c0 >> 1);
#pragma unroll
    for (int it = 0; it < 8; ++it) {
        int i = it * 256 + tid;
        int token = i >> 3, q = i & 7;
        y32[rowbase + (size_t)token * 256 + q] = sOut[token * 9 + q];
    }
}

// ===========================================================================
// Launch
// ===========================================================================
extern "C" void kernel_launch(void* const* d_in, const int* in_sizes, int n_in,
                              void* d_out, int out_size)
{
    const float* x      = (const float*)d_in[0];
    const float* msa_Wk = (const float*)d_in[1];
    const float* msa_Wv = (const float*)d_in[2];
    const float* msa_Wo = (const float*)d_in[3];
    const float* cr_Wq  = (const float*)d_in[4];
    const float* cr_bq  = (const float*)d_in[5];
    const float* cr_Wv  = (const float*)d_in[6];
    const float* cr_Wo  = (const float*)d_in[7];
    const float* dw_w   = (const float*)d_in[8];
    const float* bn_g   = (const float*)d_in[9];
    const float* bn_b   = (const float*)d_in[10];
    const float* bn_m   = (const float*)d_in[11];
    const float* bn_v   = (const float*)d_in[12];
    const float* pw_w   = (const float*)d_in[13];
    float* out = (float*)d_out;

    __half *hv, *hA, *hB, *hC, *hD, *hE, *wh;
    cudaGetSymbolAddress((void**)&hv, g_hv);
    cudaGetSymbolAddress((void**)&hA, g_hA);
    cudaGetSymbolAddress((void**)&hB, g_hB);
    cudaGetSymbolAddress((void**)&hC, g_hC);
    cudaGetSymbolAddress((void**)&hD, g_hD);
    cudaGetSymbolAddress((void**)&hE, g_hE);
    cudaGetSymbolAddress((void**)&wh, g_wh);

    cudaFuncSetAttribute(k_hgemm<0>, cudaFuncAttributeMaxDynamicSharedMemorySize, GSMEM);
    cudaFuncSetAttribute(k_hgemm<2>, cudaFuncAttributeMaxDynamicSharedMemorySize, GSMEM);
    cudaFuncSetAttribute(k_hgemm<3>, cudaFuncAttributeMaxDynamicSharedMemorySize, GSMEM);
    cudaFuncSetAttribute(k_hgemm<6>, cudaFuncAttributeMaxDynamicSharedMemorySize, GSMEM);
    cudaFuncSetAttribute(k_attn_h<false>, cudaFuncAttributeMaxDynamicSharedMemorySize, ATTN_SMEM);
    cudaFuncSetAttribute(k_attn_h<true>,  cudaFuncAttributeMaxDynamicSharedMemorySize, ATTN_SMEM);

    // 0. weights -> half
    k_w2h_all<<<(7 * WN + 255) / 256, 256>>>(msa_Wk, msa_Wv, cr_Wv, msa_Wo,
                                             cr_Wq, cr_Wo, pw_w, wh);

    dim3 tgrid(3, 16, B_ * H_), tblk(32, 8);
    dim3 ggrid(4, NTOK / 128), gblk(256);
    dim3 g6grid(12, NTOK / 128);
    dim3 dgrid(HW_ / 256, C_ / 16, B_);

    // 1. vqk = permute(x) (half)
    k_bchw_to_nhc<<<tgrid, tblk>>>(x, hv);
    // 2. fused [K|V|KV] = vqk @ [Wk|Wv|crWv]^T (K += vqk residual)
    k_hgemm<6><<<g6grid, gblk, GSMEM>>>(hv, wh, hA, hv, hB, hC);
    // 3. attn(vqk, K, V) -> hD (nhc)
    k_attn_h<false><<<B_ * W_ * NHEAD, 192, ATTN_SMEM>>>(hv, hA, hB, hD);
    // 4. O = attn@Wo^T -> hE (nhc, coalesced store)
    k_hgemm<0><<<ggrid, gblk, GSMEM>>>(hD, wh + 3 * WN, hE, nullptr, nullptr, nullptr);
    // 5. q_view = nhc->bchw(hE) -> hA (coalesced transpose; K dead)
    k_nhc_to_bchw_h<<<tgrid, tblk>>>(hE, hA);
    // 6. Q2 = q_view@crWq^T + bq -> hE
    k_hgemm<2><<<ggrid, gblk, GSMEM>>>(hA, wh + 4 * WN, hE, cr_bq, nullptr, nullptr);
    // 7. attn(Q2, KV, KV), output tokens permuted to bhw -> hB
    k_attn_h<true><<<B_ * W_ * NHEAD, 192, ATTN_SMEM>>>(hE, hC, hC, hB);
    // 8. CR = crattn@crWo^T -> hD (half, bhw token order, coalesced)
    k_hgemm<0><<<ggrid, gblk, GSMEM>>>(hB, wh + 5 * WN, hD, nullptr, nullptr, nullptr);
    // 9. depthwise+BN -> hA (half, token-major bhw)
    k_dwconv2<<<dgrid, 256>>>(x, dw_w, bn_g, bn_b, bn_m, bn_v, hA);
    // 10. out = clip(hA@pw^T,0,6) + CR(hD) -> BCHW fp32 (coalesced CR read)
    k_hgemm<3><<<ggrid, gblk, GSMEM>>>(hA, wh + 6 * WN, out, hD, nullptr, nullptr);
}